// round 10
// baseline (speedup 1.0000x reference)
#include <cuda_runtime.h>
#include <cuda_fp16.h>
#include <math.h>
#include <stdint.h>

#define SS 256       // sequence
#define CC 128       // channels
#define NH 4
#define HD 32
#define MTOT (SS*SS) // 65536
#define ATT_SCALE 0.17677669529663687f  // 1/sqrt(32)
#define LOG2E 1.4426950408889634f
#define LN_EPS 1e-5f

// ---------------- scratch ------------------------------------------------------
// floats:
//   z    : [0,         8388608)   fp32 layernorm output
//   qt   : [8388608,  12582912)   fp16 (half*), transposed row = j*S + i
//   kt   : [12582912, 16777216)   fp16
//   vt   : [16777216, 20971520)   fp16
//   gt   : [20971520, 25165824)   fp16
//   og   : [25165824, 33554432)   fp32 gated attention output
//   bias : [33554432, +131072)    fp16 [n][k][i], pre-scaled by LOG2E
__device__ float g_scratch[33685504];

__device__ __forceinline__ float fexp2(float x) {
    float r;
    asm("ex2.approx.ftz.f32 %0, %1;" : "=f"(r) : "f"(x));
    return r;
}

// pack two fp32 -> f16x2 (lo = second operand) — empirically validated in R8/R9.
__device__ __forceinline__ uint32_t f16x2(float hi, float lo) {
    uint32_t r;
    asm("cvt.rn.f16x2.f32 %0, %1, %2;" : "=r"(r) : "f"(hi), "f"(lo));
    return r;
}

__device__ __forceinline__ void mma_f16(float4& c, uint32_t a0, uint32_t a1,
                                        uint32_t a2, uint32_t a3,
                                        uint32_t b0, uint32_t b1) {
    asm volatile(
        "mma.sync.aligned.m16n8k16.row.col.f32.f16.f16.f32 "
        "{%0,%1,%2,%3}, {%4,%5,%6,%7}, {%8,%9}, {%0,%1,%2,%3};"
        : "+f"(c.x), "+f"(c.y), "+f"(c.z), "+f"(c.w)
        : "r"(a0), "r"(a1), "r"(a2), "r"(a3), "r"(b0), "r"(b1));
}

#define LDSM_X4(d0,d1,d2,d3,a) \
    asm volatile("ldmatrix.sync.aligned.m8n8.x4.shared.b16 {%0,%1,%2,%3}, [%4];" \
                 : "=r"(d0),"=r"(d1),"=r"(d2),"=r"(d3) : "r"(a))
#define LDSM_X4_T(d0,d1,d2,d3,a) \
    asm volatile("ldmatrix.sync.aligned.m8n8.x4.trans.shared.b16 {%0,%1,%2,%3}, [%4];" \
                 : "=r"(d0),"=r"(d1),"=r"(d2),"=r"(d3) : "r"(a))

#define CP_ASYNC16(dst, src) \
    asm volatile("cp.async.ca.shared.global [%0], [%1], 16;" :: "r"(dst), "l"(src))
#define CP_COMMIT() asm volatile("cp.async.commit_group;")
#define CP_WAIT(n)  asm volatile("cp.async.wait_group %0;" :: "n"(n))

// ---------------- LayerNorm: one warp per row of 128 channels -------------------
__global__ void ln_kernel(const float* __restrict__ x, const float* __restrict__ gamma,
                          const float* __restrict__ beta, float* __restrict__ z) {
    int warp = blockIdx.x * 8 + (threadIdx.x >> 5);
    int lane = threadIdx.x & 31;
    if (warp >= MTOT) return;
    const float4 v = ((const float4*)(x + (size_t)warp * CC))[lane];
    float s  = v.x + v.y + v.z + v.w;
    float sq = v.x*v.x + v.y*v.y + v.z*v.z + v.w*v.w;
    #pragma unroll
    for (int off = 16; off; off >>= 1) {
        s  += __shfl_xor_sync(0xffffffffu, s,  off);
        sq += __shfl_xor_sync(0xffffffffu, sq, off);
    }
    float mu  = s * (1.0f / CC);
    float var = sq * (1.0f / CC) - mu * mu;
    float rs  = rsqrtf(var + LN_EPS);
    const float4 g4 = ((const float4*)gamma)[lane];
    const float4 b4 = ((const float4*)beta)[lane];
    float4 o;
    o.x = (v.x - mu) * rs * g4.x + b4.x;
    o.y = (v.y - mu) * rs * g4.y + b4.y;
    o.z = (v.z - mu) * rs * g4.z + b4.z;
    o.w = (v.w - mu) * rs * g4.w + b4.w;
    ((float4*)(z + (size_t)warp * CC))[lane] = o;
}

// ---------------- fp16 MMA GEMM: [65536,128] x (up to 4x) [128,128] ------------
struct GemmArgs {
    const float* A;
    const float* W[4];
    void*        out[4];
    const float* bias[4];
    int          sig[4];
    int          h16[4];    // 1 => store output as fp16
    int          nw;
};

#define HGEMM_SMEM (3 * 17408 * 2)   // 104448 bytes

__global__ void __launch_bounds__(256, 2)
hgemm_kernel(GemmArgs ga) {
    extern __shared__ __half hsm[];
    __half* Ah = hsm;                 // 128 * 136
    __half* Bbuf0 = hsm + 17408;
    __half* Bbuf1 = hsm + 34816;
    const int t = threadIdx.x;
    const int lane = t & 31, warp = t >> 5;
    const int wm = warp & 3, wn = warp >> 2;
    const int m0w = wm * 32, n0w = wn * 64;
    const int g = lane >> 2, q = lane & 3;
    const int row0 = blockIdx.x * 128;

    #pragma unroll
    for (int i = 0; i < 16; i++) {
        int id = t + i * 256;
        int r = id >> 5, c = id & 31;
        float4 v = ((const float4*)ga.A)[(size_t)(row0 + r) * 32 + c];
        uint2 p;
        p.x = f16x2(v.y, v.x);
        p.y = f16x2(v.w, v.z);
        *(uint2*)(Ah + r * 136 + c * 4) = p;
    }
    {
        const float* W = ga.W[0];
        #pragma unroll
        for (int i = 0; i < 16; i++) {
            int id = t + i * 256;
            int kk = id >> 5, n4 = id & 31;
            float4 v = ((const float4*)W)[(size_t)kk * 32 + n4];
            uint2 p;
            p.x = f16x2(v.y, v.x);
            p.y = f16x2(v.w, v.z);
            *(uint2*)(Bbuf0 + kk * 136 + n4 * 4) = p;
        }
    }
    __syncthreads();

    uint32_t aBase[2];
    #pragma unroll
    for (int mt = 0; mt < 2; mt++)
        aBase[mt] = (uint32_t)__cvta_generic_to_shared(
            Ah + (m0w + 16 * mt + (lane & 15)) * 136 + (lane >> 4) * 8);
    const int krow_l = (lane & 7) + (((lane & 15) >> 3) << 3);
    const int ncol_l = (lane >> 4) * 8;
    uint32_t bBase[2];
    bBase[0] = (uint32_t)__cvta_generic_to_shared(Bbuf0 + krow_l * 136 + n0w + ncol_l);
    bBase[1] = (uint32_t)__cvta_generic_to_shared(Bbuf1 + krow_l * 136 + n0w + ncol_l);

    for (int w = 0; w < ga.nw; w++) {
        if (w + 1 < ga.nw) {
            __half* Bn = ((w + 1) & 1) ? Bbuf1 : Bbuf0;
            const float* W = ga.W[w + 1];
            #pragma unroll
            for (int i = 0; i < 16; i++) {
                int id = t + i * 256;
                int kk = id >> 5, n4 = id & 31;
                float4 v = ((const float4*)W)[(size_t)kk * 32 + n4];
                uint2 p;
                p.x = f16x2(v.y, v.x);
                p.y = f16x2(v.w, v.z);
                *(uint2*)(Bn + kk * 136 + n4 * 4) = p;
            }
        }

        float4 acc[2][8];
        #pragma unroll
        for (int mt = 0; mt < 2; mt++)
            #pragma unroll
            for (int nt = 0; nt < 8; nt++) acc[mt][nt] = make_float4(0.f, 0.f, 0.f, 0.f);

        const uint32_t bB = bBase[w & 1];
        #pragma unroll
        for (int step = 0; step < 8; step++) {
            uint32_t a0[4], a1[4];
            LDSM_X4(a0[0], a0[1], a0[2], a0[3], aBase[0] + step * 32);
            LDSM_X4(a1[0], a1[1], a1[2], a1[3], aBase[1] + step * 32);
            #pragma unroll
            for (int p2 = 0; p2 < 4; p2++) {
                uint32_t b0, b1, b2, b3;
                LDSM_X4_T(b0, b1, b2, b3, bB + (step * 2176 + p2 * 16) * 2);
                mma_f16(acc[0][2*p2],   a0[0], a0[1], a0[2], a0[3], b0, b1);
                mma_f16(acc[0][2*p2+1], a0[0], a0[1], a0[2], a0[3], b2, b3);
                mma_f16(acc[1][2*p2],   a1[0], a1[1], a1[2], a1[3], b0, b1);
                mma_f16(acc[1][2*p2+1], a1[0], a1[1], a1[2], a1[3], b2, b3);
            }
        }

        const float* bias = ga.bias[w];
        const int sig = ga.sig[w];
        const int h16 = ga.h16[w];
        float2 bv[8];
        #pragma unroll
        for (int nt = 0; nt < 8; nt++) {
            if (bias) bv[nt] = *(const float2*)(bias + n0w + nt * 8 + 2 * q);
            else      bv[nt] = make_float2(0.f, 0.f);
        }
        #pragma unroll
        for (int mt = 0; mt < 2; mt++) {
            int r  = row0 + m0w + mt * 16 + g;
            int r2 = r + 8;
            int or0 = ((r  & 255) << 8) | (r  >> 8);
            int or1 = ((r2 & 255) << 8) | (r2 >> 8);
            #pragma unroll
            for (int nt = 0; nt < 8; nt++) {
                int col = n0w + nt * 8 + 2 * q;
                float4 c = acc[mt][nt];
                float v0 = c.x + bv[nt].x, v1 = c.y + bv[nt].y;
                float v2 = c.z + bv[nt].x, v3 = c.w + bv[nt].y;
                if (sig) {
                    v0 = 1.0f / (1.0f + __expf(-v0));
                    v1 = 1.0f / (1.0f + __expf(-v1));
                    v2 = 1.0f / (1.0f + __expf(-v2));
                    v3 = 1.0f / (1.0f + __expf(-v3));
                }
                if (h16) {
                    __half* o = (__half*)ga.out[w];
                    *(uint32_t*)(o + (size_t)or0 * CC + col) = f16x2(v1, v0);
                    *(uint32_t*)(o + (size_t)or1 * CC + col) = f16x2(v3, v2);
                } else {
                    float* o = (float*)ga.out[w];
                    *(float2*)(o + (size_t)or0 * CC + col) = make_float2(v0, v1);
                    *(float2*)(o + (size_t)or1 * CC + col) = make_float2(v2, v3);
                }
            }
        }
        __syncthreads();
    }
}

// ---------------- attention bias projection: z @ Wb -> fp16 bias[n][k][i] ------
// stores bias * LOG2E as fp16.
__global__ void projb_kernel(const float* __restrict__ z, const float* __restrict__ Wb,
                             __half* __restrict__ bias_h) {
    int warp = blockIdx.x * 8 + (threadIdx.x >> 5);
    int lane = threadIdx.x & 31;
    if (warp >= MTOT) return;
    const float4 v = ((const float4*)(z + (size_t)warp * CC))[lane];
    float p0 = 0, p1 = 0, p2 = 0, p3 = 0;
    const float zc[4] = {v.x, v.y, v.z, v.w};
    #pragma unroll
    for (int qq = 0; qq < 4; qq++) {
        int c = lane * 4 + qq;
        p0 += zc[qq] * Wb[c * 4 + 0];
        p1 += zc[qq] * Wb[c * 4 + 1];
        p2 += zc[qq] * Wb[c * 4 + 2];
        p3 += zc[qq] * Wb[c * 4 + 3];
    }
    #pragma unroll
    for (int off = 16; off; off >>= 1) {
        p0 += __shfl_xor_sync(0xffffffffu, p0, off);
        p1 += __shfl_xor_sync(0xffffffffu, p1, off);
        p2 += __shfl_xor_sync(0xffffffffu, p2, off);
        p3 += __shfl_xor_sync(0xffffffffu, p3, off);
    }
    if (lane == 0) {
        int o = (warp & (SS - 1)) * SS + (warp >> 8);
        bias_h[0 * MTOT + o] = __float2half(p0 * LOG2E);
        bias_h[1 * MTOT + o] = __float2half(p1 * LOG2E);
        bias_h[2 * MTOT + o] = __float2half(p2 * LOG2E);
        bias_h[3 * MTOT + o] = __float2half(p3 * LOG2E);
    }
}

// ---------------- all-fp16 MMA flash attention, cp.async 2-stage pipeline ------
// One block per (j, n); 8 warps x 32 query rows; keys in 4 chunks of 64,
// double-buffered via cp.async. smem (halves):
//   Kh[2] : [0,     5120)  64x32 fp16, stride 40  (ldmatrix: banks key*20 mod 32, c-free)
//   Vh[2] : [5120, 10240)  64x32 fp16, stride 40
//   Bs[2] : [10240,44032)  64x256 fp16 bias slab, stride 264 (c-free reads)
#define ATT_SMEM_BYTES (44032 * 2)
__global__ void __launch_bounds__(256, 1)
attn_mma_kernel(const __half* __restrict__ qt, const __half* __restrict__ kt,
                const __half* __restrict__ vt, const __half* __restrict__ gt,
                const __half* __restrict__ bias_h, float* __restrict__ og) {
    extern __shared__ __half hsm2[];
    const uint32_t smemB = (uint32_t)__cvta_generic_to_shared(hsm2);

    const int j = blockIdx.x, n = blockIdx.y;
    const int t = threadIdx.x;
    const int lane = t & 31, w = t >> 5;
    const int g = lane >> 2, q = lane & 3;
    const int I0 = w * 32;
    const float SCALE2 = ATT_SCALE * LOG2E;

    // ---- Q fragments (fp16 A-frags), rows I0+16mt+g(+8), k = 16kt2+2q(+8) ----
    uint32_t qa[2][2][4];
    #pragma unroll
    for (int mt = 0; mt < 2; mt++) {
        const __half* qp0 = qt + (size_t)(j * SS + I0 + mt * 16 + g) * CC + n * HD;
        const __half* qp1 = qp0 + 8 * CC;
        #pragma unroll
        for (int kt2 = 0; kt2 < 2; kt2++) {
            qa[mt][kt2][0] = *(const uint32_t*)(qp0 + kt2 * 16 + 2 * q);
            qa[mt][kt2][1] = *(const uint32_t*)(qp1 + kt2 * 16 + 2 * q);
            qa[mt][kt2][2] = *(const uint32_t*)(qp0 + kt2 * 16 + 8 + 2 * q);
            qa[mt][kt2][3] = *(const uint32_t*)(qp1 + kt2 * 16 + 8 + 2 * q);
        }
    }

    // per-lane ldmatrix offsets (halves)
    const int koff = ((lane & 7) + ((lane >> 4) << 3)) * 40 + (((lane >> 3) & 1) << 3);
    const int voff = ((lane & 7) + (((lane >> 3) & 1) << 3)) * 40 + ((lane >> 4) << 3);

    // staging indices
    const int srow = t >> 2, sseg = t & 3;
    const size_t kvsrc0 = (size_t)(j * SS) * CC + n * HD + sseg * 8;

    float m_[2][2], l_[2][2];
    float4 o_[2][4];
    #pragma unroll
    for (int mt = 0; mt < 2; mt++) {
        m_[mt][0] = m_[mt][1] = -1e30f;
        l_[mt][0] = l_[mt][1] = 0.f;
        #pragma unroll
        for (int nt = 0; nt < 4; nt++) o_[mt][nt] = make_float4(0.f, 0.f, 0.f, 0.f);
    }

    // ---- stage(c, buf) ----
    auto stage = [&](int c, int buf) {
        uint32_t kdst = smemB + (buf * 2560 + srow * 40 + sseg * 8) * 2;
        CP_ASYNC16(kdst, kt + kvsrc0 + (size_t)(c * 64 + srow) * CC);
        uint32_t vdst = smemB + ((5120 + buf * 2560) + srow * 40 + sseg * 8) * 2;
        CP_ASYNC16(vdst, vt + kvsrc0 + (size_t)(c * 64 + srow) * CC);
        #pragma unroll
        for (int i = 0; i < 8; i++) {
            int id = t + i * 256;
            int brow = id >> 5, bseg = id & 31;
            uint32_t bdst = smemB + ((10240 + buf * 16896) + brow * 264 + bseg * 8) * 2;
            CP_ASYNC16(bdst, bias_h + (size_t)n * MTOT + (size_t)(c * 64 + brow) * SS + bseg * 8);
        }
    };

    stage(0, 0); CP_COMMIT();
    stage(1, 1); CP_COMMIT();

    for (int c = 0; c < 4; c++) {
        const int buf = c & 1;
        if (c < 3) { CP_WAIT(1); } else { CP_WAIT(0); }
        __syncthreads();

        const uint32_t kB = smemB + (buf * 2560 + koff) * 2;
        const uint32_t vB = smemB + ((5120 + buf * 2560) + voff) * 2;
        const __half* Bsl = hsm2 + 10240 + buf * 16896;

        // ---- S = Q K^T (fp16, K via plain ldmatrix from [key][d]) ----
        float4 sc[2][8];
        #pragma unroll
        for (int mt = 0; mt < 2; mt++)
            #pragma unroll
            for (int nt = 0; nt < 8; nt++) sc[mt][nt] = make_float4(0.f, 0.f, 0.f, 0.f);
        #pragma unroll
        for (int kt2 = 0; kt2 < 2; kt2++) {
            #pragma unroll
            for (int ntp = 0; ntp < 4; ntp++) {
                uint32_t b0, b1, b2, b3;
                LDSM_X4(b0, b1, b2, b3, kB + (ntp * 640 + kt2 * 16) * 2);
                mma_f16(sc[0][2*ntp],   qa[0][kt2][0], qa[0][kt2][1], qa[0][kt2][2], qa[0][kt2][3], b0, b1);
                mma_f16(sc[0][2*ntp+1], qa[0][kt2][0], qa[0][kt2][1], qa[0][kt2][2], qa[0][kt2][3], b2, b3);
                mma_f16(sc[1][2*ntp],   qa[1][kt2][0], qa[1][kt2][1], qa[1][kt2][2], qa[1][kt2][3], b0, b1);
                mma_f16(sc[1][2*ntp+1], qa[1][kt2][0], qa[1][kt2][1], qa[1][kt2][2], qa[1][kt2][3], b2, b3);
            }
        }

        // ---- bias add + chunk max ----
        float mx[2][2] = {{-1e30f, -1e30f}, {-1e30f, -1e30f}};
        #pragma unroll
        for (int mt = 0; mt < 2; mt++) {
            int i0 = I0 + mt * 16 + g;
            #pragma unroll
            for (int nt = 0; nt < 8; nt++) {
                int kl = nt * 8 + 2 * q;
                const __half* b0p = Bsl + kl * 264 + i0;
                const __half* b1p = b0p + 264;
                float4 s = sc[mt][nt];
                s.x = fmaf(s.x, SCALE2, __half2float(b0p[0]));
                s.y = fmaf(s.y, SCALE2, __half2float(b1p[0]));
                s.z = fmaf(s.z, SCALE2, __half2float(b0p[8]));
                s.w = fmaf(s.w, SCALE2, __half2float(b1p[8]));
                sc[mt][nt] = s;
                mx[mt][0] = fmaxf(mx[mt][0], fmaxf(s.x, s.y));
                mx[mt][1] = fmaxf(mx[mt][1], fmaxf(s.z, s.w));
            }
        }
        #pragma unroll
        for (int mt = 0; mt < 2; mt++)
            #pragma unroll
            for (int h = 0; h < 2; h++) {
                float v = mx[mt][h];
                v = fmaxf(v, __shfl_xor_sync(0xffffffffu, v, 1));
                v = fmaxf(v, __shfl_xor_sync(0xffffffffu, v, 2));
                mx[mt][h] = v;
            }

        float al[2][2], mn[2][2];
        #pragma unroll
        for (int mt = 0; mt < 2; mt++)
            #pragma unroll
            for (int h = 0; h < 2; h++) {
                mn[mt][h] = fmaxf(m_[mt][h], mx[mt][h]);
                al[mt][h] = fexp2(m_[mt][h] - mn[mt][h]);
                m_[mt][h] = mn[mt][h];
            }

        // ---- P = exp2(s - mn), row sums ----
        float rs_[2][2] = {{0.f, 0.f}, {0.f, 0.f}};
        #pragma unroll
        for (int mt = 0; mt < 2; mt++) {
            #pragma unroll
            for (int nt = 0; nt < 8; nt++) {
                float4 s = sc[mt][nt];
                s.x = fexp2(s.x - mn[mt][0]);
                s.y = fexp2(s.y - mn[mt][0]);
                s.z = fexp2(s.z - mn[mt][1]);
                s.w = fexp2(s.w - mn[mt][1]);
                sc[mt][nt] = s;
                rs_[mt][0] += s.x + s.y;
                rs_[mt][1] += s.z + s.w;
            }
        }
        #pragma unroll
        for (int mt = 0; mt < 2; mt++)
            #pragma unroll
            for (int h = 0; h < 2; h++) {
                float v = rs_[mt][h];
                v += __shfl_xor_sync(0xffffffffu, v, 1);
                v += __shfl_xor_sync(0xffffffffu, v, 2);
                l_[mt][h] = fmaf(l_[mt][h], al[mt][h], v);
            }

        // ---- rescale O ----
        #pragma unroll
        for (int mt = 0; mt < 2; mt++)
            #pragma unroll
            for (int nt = 0; nt < 4; nt++) {
                o_[mt][nt].x *= al[mt][0];
                o_[mt][nt].y *= al[mt][0];
                o_[mt][nt].z *= al[mt][1];
                o_[mt][nt].w *= al[mt][1];
            }

        // ---- O += P V (P packed to f16 A-frags; V via ldmatrix.trans) ----
        #pragma unroll
        for (int kt2 = 0; kt2 < 4; kt2++) {
            uint32_t pa[2][4];
            #pragma unroll
            for (int mt = 0; mt < 2; mt++) {
                float4 p0 = sc[mt][2 * kt2];
                float4 p1 = sc[mt][2 * kt2 + 1];
                pa[mt][0] = f16x2(p0.y, p0.x);
                pa[mt][1] = f16x2(p0.w, p0.z);
                pa[mt][2] = f16x2(p1.y, p1.x);
                pa[mt][3] = f16x2(p1.w, p1.z);
            }
            #pragma unroll
            for (int db = 0; db < 2; db++) {
                uint32_t b0, b1, b2, b3;
                LDSM_X4_T(b0, b1, b2, b3, vB + (kt2 * 640 + db * 16) * 2);
                mma_f16(o_[0][2*db],   pa[0][0], pa[0][1], pa[0][2], pa[0][3], b0, b1);
                mma_f16(o_[0][2*db+1], pa[0][0], pa[0][1], pa[0][2], pa[0][3], b2, b3);
                mma_f16(o_[1][2*db],   pa[1][0], pa[1][1], pa[1][2], pa[1][3], b0, b1);
                mma_f16(o_[1][2*db+1], pa[1][0], pa[1][1], pa[1][2], pa[1][3], b2, b3);
            }
        }

        __syncthreads();
        if (c + 2 < 4) { stage(c + 2, buf); CP_COMMIT(); }
    }

    // ---- epilogue: O/l, gate (fp16), store fp32 ----
    #pragma unroll
    for (int mt = 0; mt < 2; mt++) {
        float i0v = 1.f / l_[mt][0];
        float i1v = 1.f / l_[mt][1];
        size_t r0 = (size_t)(j * SS + I0 + mt * 16 + g) * CC + n * HD;
        size_t r1 = r0 + 8 * CC;
        #pragma unroll
        for (int nt2 = 0; nt2 < 4; nt2++) {
            int col = nt2 * 8 + 2 * q;
            float2 g0 = __half22float2(*(const __half2*)(gt + r0 + col));
            float2 g1 = __half22float2(*(const __half2*)(gt + r1 + col));
            float4 o4 = o_[mt][nt2];
            *(float2*)(og + r0 + col) = make_float2(o4.x * i0v * g0.x, o4.y * i0v * g0.y);
            *(float2*)(og + r1 + col) = make_float2(o4.z * i1v * g1.x, o4.w * i1v * g1.y);
        }
    }
}

// ---------------- launch -------------------------------------------------------
extern "C" void kernel_launch(void* const* d_in, const int* in_sizes, int n_in,
                              void* d_out, int out_size) {
    const float* pair  = (const float*)d_in[0];
    const float* gamma = (const float*)d_in[1];
    const float* beta  = (const float*)d_in[2];
    const float* Wq    = (const float*)d_in[3];
    const float* Wk    = (const float*)d_in[4];
    const float* Wv    = (const float*)d_in[5];
    const float* Wb    = (const float*)d_in[6];
    const float* Wg    = (const float*)d_in[7];
    const float* bg    = (const float*)d_in[8];
    const float* Wo    = (const float*)d_in[9];
    const float* bo    = (const float*)d_in[10];
    float* out = (float*)d_out;

    float* base = nullptr;
    cudaGetSymbolAddress((void**)&base, g_scratch);
    float*  z      = base;
    __half* qt     = (__half*)(base + 8388608);
    __half* kt     = (__half*)(base + 12582912);
    __half* vt     = (__half*)(base + 16777216);
    __half* gt     = (__half*)(base + 20971520);
    float*  og     = base + 25165824;
    __half* bias_h = (__half*)(base + 33554432);

    cudaFuncSetAttribute(hgemm_kernel,
                         cudaFuncAttributeMaxDynamicSharedMemorySize, HGEMM_SMEM);
    cudaFuncSetAttribute(attn_mma_kernel,
                         cudaFuncAttributeMaxDynamicSharedMemorySize, ATT_SMEM_BYTES);

    ln_kernel<<<MTOT / 8, 256>>>(pair, gamma, beta, z);

    GemmArgs pa;
    pa.A = z;
    pa.W[0] = Wq; pa.W[1] = Wk; pa.W[2] = Wv; pa.W[3] = Wg;
    pa.out[0] = qt; pa.out[1] = kt; pa.out[2] = vt; pa.out[3] = gt;
    pa.bias[0] = nullptr; pa.bias[1] = nullptr; pa.bias[2] = nullptr; pa.bias[3] = bg;
    pa.sig[0] = 0; pa.sig[1] = 0; pa.sig[2] = 0; pa.sig[3] = 1;
    pa.h16[0] = 1; pa.h16[1] = 1; pa.h16[2] = 1; pa.h16[3] = 1;
    pa.nw = 4;
    hgemm_kernel<<<MTOT / 128, 256, HGEMM_SMEM>>>(pa);

    projb_kernel<<<MTOT / 8, 256>>>(z, Wb, bias_h);

    attn_mma_kernel<<<dim3(SS, NH), 256, ATT_SMEM_BYTES>>>(qt, kt, vt, gt, bias_h, og);

    GemmArgs oa;
    oa.A = og;
    oa.W[0] = Wo;
    oa.out[0] = out;
    oa.bias[0] = bo;
    oa.sig[0] = 0;
    oa.h16[0] = 0;
    oa.nw = 1;
    hgemm_kernel<<<MTOT / 128, 256, HGEMM_SMEM>>>(oa);
}

// round 11
// speedup vs baseline: 1.5530x; 1.5530x over previous
#include <cuda_runtime.h>
#include <cuda_fp16.h>
#include <math.h>
#include <stdint.h>

#define SS 256       // sequence
#define CC 128       // channels
#define NH 4
#define HD 32
#define MTOT (SS*SS) // 65536
#define ATT_SCALE 0.17677669529663687f  // 1/sqrt(32)
#define LOG2E 1.4426950408889634f
#define LN_EPS 1e-5f

// ---------------- scratch ------------------------------------------------------
// floats:
//   z    : [0,         8388608)   fp32 layernorm output
//   qt   : [8388608,  12582912)   fp16 (half*), transposed row = j*S + i  (pre-scaled by ATT_SCALE*LOG2E)
//   kt   : [12582912, 16777216)   fp16
//   vt   : [16777216, 20971520)   fp16
//   gt   : [20971520, 25165824)   fp16
//   og   : [25165824, 33554432)   fp32 gated attention output
//   bias : [33554432, +131072)    fp16 [n][k][i], pre-scaled by LOG2E
__device__ float g_scratch[33685504];

__device__ __forceinline__ float fexp2(float x) {
    float r;
    asm("ex2.approx.ftz.f32 %0, %1;" : "=f"(r) : "f"(x));
    return r;
}

// pack two fp32 -> f16x2 (lo = second operand) — empirically validated in R8/R9.
__device__ __forceinline__ uint32_t f16x2(float hi, float lo) {
    uint32_t r;
    asm("cvt.rn.f16x2.f32 %0, %1, %2;" : "=r"(r) : "f"(hi), "f"(lo));
    return r;
}

__device__ __forceinline__ void mma_f16(float4& c, uint32_t a0, uint32_t a1,
                                        uint32_t a2, uint32_t a3,
                                        uint32_t b0, uint32_t b1) {
    asm volatile(
        "mma.sync.aligned.m16n8k16.row.col.f32.f16.f16.f32 "
        "{%0,%1,%2,%3}, {%4,%5,%6,%7}, {%8,%9}, {%0,%1,%2,%3};"
        : "+f"(c.x), "+f"(c.y), "+f"(c.z), "+f"(c.w)
        : "r"(a0), "r"(a1), "r"(a2), "r"(a3), "r"(b0), "r"(b1));
}

#define LDSM_X4(d0,d1,d2,d3,a) \
    asm volatile("ldmatrix.sync.aligned.m8n8.x4.shared.b16 {%0,%1,%2,%3}, [%4];" \
                 : "=r"(d0),"=r"(d1),"=r"(d2),"=r"(d3) : "r"(a))
#define LDSM_X4_T(d0,d1,d2,d3,a) \
    asm volatile("ldmatrix.sync.aligned.m8n8.x4.trans.shared.b16 {%0,%1,%2,%3}, [%4];" \
                 : "=r"(d0),"=r"(d1),"=r"(d2),"=r"(d3) : "r"(a))

#define CP_ASYNC16(dst, src) \
    asm volatile("cp.async.ca.shared.global [%0], [%1], 16;" :: "r"(dst), "l"(src))
#define CP_COMMIT() asm volatile("cp.async.commit_group;")
#define CP_WAIT(n)  asm volatile("cp.async.wait_group %0;" :: "n"(n))

// ---------------- LayerNorm: one warp per row of 128 channels -------------------
__global__ void ln_kernel(const float* __restrict__ x, const float* __restrict__ gamma,
                          const float* __restrict__ beta, float* __restrict__ z) {
    int warp = blockIdx.x * 8 + (threadIdx.x >> 5);
    int lane = threadIdx.x & 31;
    if (warp >= MTOT) return;
    const float4 v = ((const float4*)(x + (size_t)warp * CC))[lane];
    float s  = v.x + v.y + v.z + v.w;
    float sq = v.x*v.x + v.y*v.y + v.z*v.z + v.w*v.w;
    #pragma unroll
    for (int off = 16; off; off >>= 1) {
        s  += __shfl_xor_sync(0xffffffffu, s,  off);
        sq += __shfl_xor_sync(0xffffffffu, sq, off);
    }
    float mu  = s * (1.0f / CC);
    float var = sq * (1.0f / CC) - mu * mu;
    float rs  = rsqrtf(var + LN_EPS);
    const float4 g4 = ((const float4*)gamma)[lane];
    const float4 b4 = ((const float4*)beta)[lane];
    float4 o;
    o.x = (v.x - mu) * rs * g4.x + b4.x;
    o.y = (v.y - mu) * rs * g4.y + b4.y;
    o.z = (v.z - mu) * rs * g4.z + b4.z;
    o.w = (v.w - mu) * rs * g4.w + b4.w;
    ((float4*)(z + (size_t)warp * CC))[lane] = o;
}

// ---------------- fp16 MMA GEMM: [65536,128] x (up to 4x) [128,128] ------------
// H16 is a compile-time template parameter: no dual store path in the binary
// (the runtime branch in R10 pushed the 128-reg-capped kernel into spills).
struct GemmArgs {
    const float* A;
    const float* W[4];
    void*        out[4];
    const float* bias[4];
    float        oscale[4];  // output scale (1.0 normally)
    int          sig[4];
    int          nw;
};

#define HGEMM_SMEM (3 * 17408 * 2)   // 104448 bytes

template<int H16>
__global__ void __launch_bounds__(256, 2)
hgemm_kernel(GemmArgs ga) {
    extern __shared__ __half hsm[];
    __half* Ah = hsm;                 // 128 * 136
    __half* Bbuf0 = hsm + 17408;
    __half* Bbuf1 = hsm + 34816;
    const int t = threadIdx.x;
    const int lane = t & 31, warp = t >> 5;
    const int wm = warp & 3, wn = warp >> 2;
    const int m0w = wm * 32, n0w = wn * 64;
    const int g = lane >> 2, q = lane & 3;
    const int row0 = blockIdx.x * 128;

    #pragma unroll
    for (int i = 0; i < 16; i++) {
        int id = t + i * 256;
        int r = id >> 5, c = id & 31;
        float4 v = ((const float4*)ga.A)[(size_t)(row0 + r) * 32 + c];
        uint2 p;
        p.x = f16x2(v.y, v.x);
        p.y = f16x2(v.w, v.z);
        *(uint2*)(Ah + r * 136 + c * 4) = p;
    }
    {
        const float* W = ga.W[0];
        #pragma unroll
        for (int i = 0; i < 16; i++) {
            int id = t + i * 256;
            int kk = id >> 5, n4 = id & 31;
            float4 v = ((const float4*)W)[(size_t)kk * 32 + n4];
            uint2 p;
            p.x = f16x2(v.y, v.x);
            p.y = f16x2(v.w, v.z);
            *(uint2*)(Bbuf0 + kk * 136 + n4 * 4) = p;
        }
    }
    __syncthreads();

    uint32_t aBase[2];
    #pragma unroll
    for (int mt = 0; mt < 2; mt++)
        aBase[mt] = (uint32_t)__cvta_generic_to_shared(
            Ah + (m0w + 16 * mt + (lane & 15)) * 136 + (lane >> 4) * 8);
    const int krow_l = (lane & 7) + (((lane & 15) >> 3) << 3);
    const int ncol_l = (lane >> 4) * 8;
    uint32_t bBase[2];
    bBase[0] = (uint32_t)__cvta_generic_to_shared(Bbuf0 + krow_l * 136 + n0w + ncol_l);
    bBase[1] = (uint32_t)__cvta_generic_to_shared(Bbuf1 + krow_l * 136 + n0w + ncol_l);

    for (int w = 0; w < ga.nw; w++) {
        if (w + 1 < ga.nw) {
            __half* Bn = ((w + 1) & 1) ? Bbuf1 : Bbuf0;
            const float* W = ga.W[w + 1];
            #pragma unroll
            for (int i = 0; i < 16; i++) {
                int id = t + i * 256;
                int kk = id >> 5, n4 = id & 31;
                float4 v = ((const float4*)W)[(size_t)kk * 32 + n4];
                uint2 p;
                p.x = f16x2(v.y, v.x);
                p.y = f16x2(v.w, v.z);
                *(uint2*)(Bn + kk * 136 + n4 * 4) = p;
            }
        }

        float4 acc[2][8];
        #pragma unroll
        for (int mt = 0; mt < 2; mt++)
            #pragma unroll
            for (int nt = 0; nt < 8; nt++) acc[mt][nt] = make_float4(0.f, 0.f, 0.f, 0.f);

        const uint32_t bB = bBase[w & 1];
        #pragma unroll
        for (int step = 0; step < 8; step++) {
            uint32_t a0[4], a1[4];
            LDSM_X4(a0[0], a0[1], a0[2], a0[3], aBase[0] + step * 32);
            LDSM_X4(a1[0], a1[1], a1[2], a1[3], aBase[1] + step * 32);
            #pragma unroll
            for (int p2 = 0; p2 < 4; p2++) {
                uint32_t b0, b1, b2, b3;
                LDSM_X4_T(b0, b1, b2, b3, bB + (step * 2176 + p2 * 16) * 2);
                mma_f16(acc[0][2*p2],   a0[0], a0[1], a0[2], a0[3], b0, b1);
                mma_f16(acc[0][2*p2+1], a0[0], a0[1], a0[2], a0[3], b2, b3);
                mma_f16(acc[1][2*p2],   a1[0], a1[1], a1[2], a1[3], b0, b1);
                mma_f16(acc[1][2*p2+1], a1[0], a1[1], a1[2], a1[3], b2, b3);
            }
        }

        const float* bias = ga.bias[w];
        const int sig = ga.sig[w];
        const float osc = ga.oscale[w];
        float2 bv[8];
        #pragma unroll
        for (int nt = 0; nt < 8; nt++) {
            if (bias) bv[nt] = *(const float2*)(bias + n0w + nt * 8 + 2 * q);
            else      bv[nt] = make_float2(0.f, 0.f);
        }
        #pragma unroll
        for (int mt = 0; mt < 2; mt++) {
            int r  = row0 + m0w + mt * 16 + g;
            int r2 = r + 8;
            int or0 = ((r  & 255) << 8) | (r  >> 8);
            int or1 = ((r2 & 255) << 8) | (r2 >> 8);
            #pragma unroll
            for (int nt = 0; nt < 8; nt++) {
                int col = n0w + nt * 8 + 2 * q;
                float4 c = acc[mt][nt];
                float v0 = (c.x + bv[nt].x) * osc, v1 = (c.y + bv[nt].y) * osc;
                float v2 = (c.z + bv[nt].x) * osc, v3 = (c.w + bv[nt].y) * osc;
                if (sig) {
                    v0 = 1.0f / (1.0f + __expf(-v0));
                    v1 = 1.0f / (1.0f + __expf(-v1));
                    v2 = 1.0f / (1.0f + __expf(-v2));
                    v3 = 1.0f / (1.0f + __expf(-v3));
                }
                if (H16) {
                    __half* o = (__half*)ga.out[w];
                    *(uint32_t*)(o + (size_t)or0 * CC + col) = f16x2(v1, v0);
                    *(uint32_t*)(o + (size_t)or1 * CC + col) = f16x2(v3, v2);
                } else {
                    float* o = (float*)ga.out[w];
                    *(float2*)(o + (size_t)or0 * CC + col) = make_float2(v0, v1);
                    *(float2*)(o + (size_t)or1 * CC + col) = make_float2(v2, v3);
                }
            }
        }
        __syncthreads();
    }
}

// ---------------- attention bias projection: z @ Wb -> fp16 bias[n][k][i] ------
// stores bias * LOG2E as fp16.
__global__ void projb_kernel(const float* __restrict__ z, const float* __restrict__ Wb,
                             __half* __restrict__ bias_h) {
    int warp = blockIdx.x * 8 + (threadIdx.x >> 5);
    int lane = threadIdx.x & 31;
    if (warp >= MTOT) return;
    const float4 v = ((const float4*)(z + (size_t)warp * CC))[lane];
    float p0 = 0, p1 = 0, p2 = 0, p3 = 0;
    const float zc[4] = {v.x, v.y, v.z, v.w};
    #pragma unroll
    for (int qq = 0; qq < 4; qq++) {
        int c = lane * 4 + qq;
        p0 += zc[qq] * Wb[c * 4 + 0];
        p1 += zc[qq] * Wb[c * 4 + 1];
        p2 += zc[qq] * Wb[c * 4 + 2];
        p3 += zc[qq] * Wb[c * 4 + 3];
    }
    #pragma unroll
    for (int off = 16; off; off >>= 1) {
        p0 += __shfl_xor_sync(0xffffffffu, p0, off);
        p1 += __shfl_xor_sync(0xffffffffu, p1, off);
        p2 += __shfl_xor_sync(0xffffffffu, p2, off);
        p3 += __shfl_xor_sync(0xffffffffu, p3, off);
    }
    if (lane == 0) {
        int o = (warp & (SS - 1)) * SS + (warp >> 8);
        bias_h[0 * MTOT + o] = __float2half(p0 * LOG2E);
        bias_h[1 * MTOT + o] = __float2half(p1 * LOG2E);
        bias_h[2 * MTOT + o] = __float2half(p2 * LOG2E);
        bias_h[3 * MTOT + o] = __float2half(p3 * LOG2E);
    }
}

// ---------------- all-fp16 MMA flash attention ---------------------------------
// 128-thread CTAs (4 warps x 32 query rows = 128 rows each), 2 CTAs/SM.
// Grid (j=256, ih=2, n=4). Keys in 4 chunks of 64, cp.async double-buffered.
// Q is pre-scaled by ATT_SCALE*LOG2E (hgemm oscale); bias initializes the
// S accumulator (no separate bias-add FMAs).
// smem (halves):
//   Kh[2] : [0,     5120)  64x32 fp16, stride 40
//   Vh[2] : [5120, 10240)  64x32 fp16, stride 40
//   Bs[2] : [10240,27648)  64x128 fp16 bias slab, stride 136 (c-free reads)
#define ATT_SMEM_BYTES (27648 * 2)   // 55296 bytes
__global__ void __launch_bounds__(128, 2)
attn_mma_kernel(const __half* __restrict__ qt, const __half* __restrict__ kt,
                const __half* __restrict__ vt, const __half* __restrict__ gt,
                const __half* __restrict__ bias_h, float* __restrict__ og) {
    extern __shared__ __half hsm2[];
    const uint32_t smemB = (uint32_t)__cvta_generic_to_shared(hsm2);

    const int j = blockIdx.x, ih = blockIdx.y, n = blockIdx.z;
    const int t = threadIdx.x;
    const int lane = t & 31, w = t >> 5;
    const int g = lane >> 2, q = lane & 3;
    const int I0 = ih * 128 + w * 32;

    // ---- Q fragments (fp16 A-frags, pre-scaled) ----
    uint32_t qa[2][2][4];
    #pragma unroll
    for (int mt = 0; mt < 2; mt++) {
        const __half* qp0 = qt + (size_t)(j * SS + I0 + mt * 16 + g) * CC + n * HD;
        const __half* qp1 = qp0 + 8 * CC;
        #pragma unroll
        for (int kt2 = 0; kt2 < 2; kt2++) {
            qa[mt][kt2][0] = *(const uint32_t*)(qp0 + kt2 * 16 + 2 * q);
            qa[mt][kt2][1] = *(const uint32_t*)(qp1 + kt2 * 16 + 2 * q);
            qa[mt][kt2][2] = *(const uint32_t*)(qp0 + kt2 * 16 + 8 + 2 * q);
            qa[mt][kt2][3] = *(const uint32_t*)(qp1 + kt2 * 16 + 8 + 2 * q);
        }
    }

    const int koff = ((lane & 7) + ((lane >> 4) << 3)) * 40 + (((lane >> 3) & 1) << 3);
    const int voff = ((lane & 7) + (((lane >> 3) & 1) << 3)) * 40 + ((lane >> 4) << 3);
    const size_t kvbase = (size_t)(j * SS) * CC + n * HD;

    float m_[2][2], l_[2][2];
    float4 o_[2][4];
    #pragma unroll
    for (int mt = 0; mt < 2; mt++) {
        m_[mt][0] = m_[mt][1] = -1e30f;
        l_[mt][0] = l_[mt][1] = 0.f;
        #pragma unroll
        for (int nt = 0; nt < 4; nt++) o_[mt][nt] = make_float4(0.f, 0.f, 0.f, 0.f);
    }

    auto stage = [&](int c, int buf) {
        #pragma unroll
        for (int i = 0; i < 2; i++) {
            int id = t + i * 128;
            int row = id >> 2, seg = id & 3;
            uint32_t kdst = smemB + (buf * 2560 + row * 40 + seg * 8) * 2;
            CP_ASYNC16(kdst, kt + kvbase + (size_t)(c * 64 + row) * CC + seg * 8);
            uint32_t vdst = smemB + ((5120 + buf * 2560) + row * 40 + seg * 8) * 2;
            CP_ASYNC16(vdst, vt + kvbase + (size_t)(c * 64 + row) * CC + seg * 8);
        }
        #pragma unroll
        for (int i = 0; i < 8; i++) {
            int id = t + i * 128;
            int brow = id >> 4, bseg = id & 15;
            uint32_t bdst = smemB + ((10240 + buf * 8704) + brow * 136 + bseg * 8) * 2;
            CP_ASYNC16(bdst, bias_h + (size_t)n * MTOT +
                             (size_t)(c * 64 + brow) * SS + ih * 128 + bseg * 8);
        }
    };

    stage(0, 0); CP_COMMIT();
    stage(1, 1); CP_COMMIT();

    for (int c = 0; c < 4; c++) {
        const int buf = c & 1;
        if (c < 3) { CP_WAIT(1); } else { CP_WAIT(0); }
        __syncthreads();

        const uint32_t kB = smemB + (buf * 2560 + koff) * 2;
        const uint32_t vB = smemB + ((5120 + buf * 2560) + voff) * 2;
        const __half* Bsl = hsm2 + 10240 + buf * 8704;

        // ---- init S accumulator from bias slab ----
        float4 sc[2][8];
        #pragma unroll
        for (int mt = 0; mt < 2; mt++) {
            int i0l = w * 32 + mt * 16 + g;
            #pragma unroll
            for (int nt = 0; nt < 8; nt++) {
                int kl = nt * 8 + 2 * q;
                const __half* b0p = Bsl + kl * 136 + i0l;
                const __half* b1p = b0p + 136;
                sc[mt][nt].x = __half2float(b0p[0]);
                sc[mt][nt].y = __half2float(b1p[0]);
                sc[mt][nt].z = __half2float(b0p[8]);
                sc[mt][nt].w = __half2float(b1p[8]);
            }
        }

        // ---- S = bias + Q' K^T (fp16) ----
        #pragma unroll
        for (int kt2 = 0; kt2 < 2; kt2++) {
            #pragma unroll
            for (int ntp = 0; ntp < 4; ntp++) {
                uint32_t b0, b1, b2, b3;
                LDSM_X4(b0, b1, b2, b3, kB + (ntp * 640 + kt2 * 16) * 2);
                mma_f16(sc[0][2*ntp],   qa[0][kt2][0], qa[0][kt2][1], qa[0][kt2][2], qa[0][kt2][3], b0, b1);
                mma_f16(sc[0][2*ntp+1], qa[0][kt2][0], qa[0][kt2][1], qa[0][kt2][2], qa[0][kt2][3], b2, b3);
                mma_f16(sc[1][2*ntp],   qa[1][kt2][0], qa[1][kt2][1], qa[1][kt2][2], qa[1][kt2][3], b0, b1);
                mma_f16(sc[1][2*ntp+1], qa[1][kt2][0], qa[1][kt2][1], qa[1][kt2][2], qa[1][kt2][3], b2, b3);
            }
        }

        // ---- chunk max ----
        float mx[2][2] = {{-1e30f, -1e30f}, {-1e30f, -1e30f}};
        #pragma unroll
        for (int mt = 0; mt < 2; mt++)
            #pragma unroll
            for (int nt = 0; nt < 8; nt++) {
                float4 s = sc[mt][nt];
                mx[mt][0] = fmaxf(mx[mt][0], fmaxf(s.x, s.y));
                mx[mt][1] = fmaxf(mx[mt][1], fmaxf(s.z, s.w));
            }
        #pragma unroll
        for (int mt = 0; mt < 2; mt++)
            #pragma unroll
            for (int h = 0; h < 2; h++) {
                float v = mx[mt][h];
                v = fmaxf(v, __shfl_xor_sync(0xffffffffu, v, 1));
                v = fmaxf(v, __shfl_xor_sync(0xffffffffu, v, 2));
                mx[mt][h] = v;
            }

        float al[2][2], mn[2][2];
        #pragma unroll
        for (int mt = 0; mt < 2; mt++)
            #pragma unroll
            for (int h = 0; h < 2; h++) {
                mn[mt][h] = fmaxf(m_[mt][h], mx[mt][h]);
                al[mt][h] = fexp2(m_[mt][h] - mn[mt][h]);
                m_[mt][h] = mn[mt][h];
            }

        // ---- P = exp2(s - mn), row sums ----
        float rs_[2][2] = {{0.f, 0.f}, {0.f, 0.f}};
        #pragma unroll
        for (int mt = 0; mt < 2; mt++) {
            #pragma unroll
            for (int nt = 0; nt < 8; nt++) {
                float4 s = sc[mt][nt];
                s.x = fexp2(s.x - mn[mt][0]);
                s.y = fexp2(s.y - mn[mt][0]);
                s.z = fexp2(s.z - mn[mt][1]);
                s.w = fexp2(s.w - mn[mt][1]);
                sc[mt][nt] = s;
                rs_[mt][0] += s.x + s.y;
                rs_[mt][1] += s.z + s.w;
            }
        }
        #pragma unroll
        for (int mt = 0; mt < 2; mt++)
            #pragma unroll
            for (int h = 0; h < 2; h++) {
                float v = rs_[mt][h];
                v += __shfl_xor_sync(0xffffffffu, v, 1);
                v += __shfl_xor_sync(0xffffffffu, v, 2);
                l_[mt][h] = fmaf(l_[mt][h], al[mt][h], v);
            }

        // ---- rescale O ----
        #pragma unroll
        for (int mt = 0; mt < 2; mt++)
            #pragma unroll
            for (int nt = 0; nt < 4; nt++) {
                o_[mt][nt].x *= al[mt][0];
                o_[mt][nt].y *= al[mt][0];
                o_[mt][nt].z *= al[mt][1];
                o_[mt][nt].w *= al[mt][1];
            }

        // ---- O += P V (P packed to f16 A-frags; V via ldmatrix.trans) ----
        #pragma unroll
        for (int kt2 = 0; kt2 < 4; kt2++) {
            uint32_t pa[2][4];
            #pragma unroll
            for (int mt = 0; mt < 2; mt++) {
                float4 p0 = sc[mt][2 * kt2];
                float4 p1 = sc[mt][2 * kt2 + 1];
                pa[mt][0] = f16x2(p0.y, p0.x);
                pa[mt][1] = f16x2(p0.w, p0.z);
                pa[mt][2] = f16x2(p1.y, p1.x);
                pa[mt][3] = f16x2(p1.w, p1.z);
            }
            #pragma unroll
            for (int db = 0; db < 2; db++) {
                uint32_t b0, b1, b2, b3;
                LDSM_X4_T(b0, b1, b2, b3, vB + (kt2 * 640 + db * 16) * 2);
                mma_f16(o_[0][2*db],   pa[0][0], pa[0][1], pa[0][2], pa[0][3], b0, b1);
                mma_f16(o_[0][2*db+1], pa[0][0], pa[0][1], pa[0][2], pa[0][3], b2, b3);
                mma_f16(o_[1][2*db],   pa[1][0], pa[1][1], pa[1][2], pa[1][3], b0, b1);
                mma_f16(o_[1][2*db+1], pa[1][0], pa[1][1], pa[1][2], pa[1][3], b2, b3);
            }
        }

        __syncthreads();
        if (c + 2 < 4) { stage(c + 2, buf); CP_COMMIT(); }
    }

    // ---- epilogue: O/l, gate (fp16), store fp32 ----
    #pragma unroll
    for (int mt = 0; mt < 2; mt++) {
        float i0v = 1.f / l_[mt][0];
        float i1v = 1.f / l_[mt][1];
        size_t r0 = (size_t)(j * SS + I0 + mt * 16 + g) * CC + n * HD;
        size_t r1 = r0 + 8 * CC;
        #pragma unroll
        for (int nt2 = 0; nt2 < 4; nt2++) {
            int col = nt2 * 8 + 2 * q;
            float2 g0 = __half22float2(*(const __half2*)(gt + r0 + col));
            float2 g1 = __half22float2(*(const __half2*)(gt + r1 + col));
            float4 o4 = o_[mt][nt2];
            *(float2*)(og + r0 + col) = make_float2(o4.x * i0v * g0.x, o4.y * i0v * g0.y);
            *(float2*)(og + r1 + col) = make_float2(o4.z * i1v * g1.x, o4.w * i1v * g1.y);
        }
    }
}

// ---------------- launch -------------------------------------------------------
extern "C" void kernel_launch(void* const* d_in, const int* in_sizes, int n_in,
                              void* d_out, int out_size) {
    const float* pair  = (const float*)d_in[0];
    const float* gamma = (const float*)d_in[1];
    const float* beta  = (const float*)d_in[2];
    const float* Wq    = (const float*)d_in[3];
    const float* Wk    = (const float*)d_in[4];
    const float* Wv    = (const float*)d_in[5];
    const float* Wb    = (const float*)d_in[6];
    const float* Wg    = (const float*)d_in[7];
    const float* bg    = (const float*)d_in[8];
    const float* Wo    = (const float*)d_in[9];
    const float* bo    = (const float*)d_in[10];
    float* out = (float*)d_out;

    float* base = nullptr;
    cudaGetSymbolAddress((void**)&base, g_scratch);
    float*  z      = base;
    __half* qt     = (__half*)(base + 8388608);
    __half* kt     = (__half*)(base + 12582912);
    __half* vt     = (__half*)(base + 16777216);
    __half* gt     = (__half*)(base + 20971520);
    float*  og     = base + 25165824;
    __half* bias_h = (__half*)(base + 33554432);

    cudaFuncSetAttribute(hgemm_kernel<1>,
                         cudaFuncAttributeMaxDynamicSharedMemorySize, HGEMM_SMEM);
    cudaFuncSetAttribute(hgemm_kernel<0>,
                         cudaFuncAttributeMaxDynamicSharedMemorySize, HGEMM_SMEM);
    cudaFuncSetAttribute(attn_mma_kernel,
                         cudaFuncAttributeMaxDynamicSharedMemorySize, ATT_SMEM_BYTES);

    ln_kernel<<<MTOT / 8, 256>>>(pair, gamma, beta, z);

    GemmArgs pa;
    pa.A = z;
    pa.W[0] = Wq; pa.W[1] = Wk; pa.W[2] = Wv; pa.W[3] = Wg;
    pa.out[0] = qt; pa.out[1] = kt; pa.out[2] = vt; pa.out[3] = gt;
    pa.bias[0] = nullptr; pa.bias[1] = nullptr; pa.bias[2] = nullptr; pa.bias[3] = bg;
    pa.oscale[0] = ATT_SCALE * LOG2E; pa.oscale[1] = 1.f; pa.oscale[2] = 1.f; pa.oscale[3] = 1.f;
    pa.sig[0] = 0; pa.sig[1] = 0; pa.sig[2] = 0; pa.sig[3] = 1;
    pa.nw = 4;
    hgemm_kernel<1><<<MTOT / 128, 256, HGEMM_SMEM>>>(pa);

    projb_kernel<<<MTOT / 8, 256>>>(z, Wb, bias_h);

    attn_mma_kernel<<<dim3(SS, 2, NH), 128, ATT_SMEM_BYTES>>>(qt, kt, vt, gt, bias_h, og);

    GemmArgs oa;
    oa.A = og;
    oa.W[0] = Wo;
    oa.out[0] = out;
    oa.bias[0] = bo;
    oa.oscale[0] = 1.f;
    oa.sig[0] = 0;
    oa.nw = 1;
    hgemm_kernel<0><<<MTOT / 128, 256, HGEMM_SMEM>>>(oa);
}

// round 12
// speedup vs baseline: 2.0318x; 1.3084x over previous
#include <cuda_runtime.h>
#include <cuda_fp16.h>
#include <math.h>
#include <stdint.h>

#define SS 256       // sequence
#define CC 128       // channels
#define NH 4
#define HD 32
#define MTOT (SS*SS) // 65536
#define ATT_SCALE 0.17677669529663687f  // 1/sqrt(32)
#define LOG2E 1.4426950408889634f
#define LN_EPS 1e-5f

// ---------------- scratch ------------------------------------------------------
// floats:
//   qt   : [0,        4194304)   fp16 (half*), transposed row = j*S + i  (pre-scaled by ATT_SCALE*LOG2E)
//   kt   : [4194304,  8388608)   fp16
//   vt   : [8388608, 12582912)   fp16
//   gt   : [12582912,16777216)   fp16
//   og   : [16777216,25165824)   fp32 gated attention output
//   bias : [25165824, +131072)   fp16 [n][k][i], pre-scaled by LOG2E
__device__ float g_scratch[25296896];

__device__ __forceinline__ float fexp2(float x) {
    float r;
    asm("ex2.approx.ftz.f32 %0, %1;" : "=f"(r) : "f"(x));
    return r;
}

// pack two fp32 -> f16x2 (lo = second operand) — empirically validated in R8/R9.
__device__ __forceinline__ uint32_t f16x2(float hi, float lo) {
    uint32_t r;
    asm("cvt.rn.f16x2.f32 %0, %1, %2;" : "=r"(r) : "f"(hi), "f"(lo));
    return r;
}

__device__ __forceinline__ void mma_f16(float4& c, uint32_t a0, uint32_t a1,
                                        uint32_t a2, uint32_t a3,
                                        uint32_t b0, uint32_t b1) {
    asm volatile(
        "mma.sync.aligned.m16n8k16.row.col.f32.f16.f16.f32 "
        "{%0,%1,%2,%3}, {%4,%5,%6,%7}, {%8,%9}, {%0,%1,%2,%3};"
        : "+f"(c.x), "+f"(c.y), "+f"(c.z), "+f"(c.w)
        : "r"(a0), "r"(a1), "r"(a2), "r"(a3), "r"(b0), "r"(b1));
}

#define LDSM_X4(d0,d1,d2,d3,a) \
    asm volatile("ldmatrix.sync.aligned.m8n8.x4.shared.b16 {%0,%1,%2,%3}, [%4];" \
                 : "=r"(d0),"=r"(d1),"=r"(d2),"=r"(d3) : "r"(a))
#define LDSM_X4_T(d0,d1,d2,d3,a) \
    asm volatile("ldmatrix.sync.aligned.m8n8.x4.trans.shared.b16 {%0,%1,%2,%3}, [%4];" \
                 : "=r"(d0),"=r"(d1),"=r"(d2),"=r"(d3) : "r"(a))

#define CP_ASYNC16(dst, src) \
    asm volatile("cp.async.ca.shared.global [%0], [%1], 16;" :: "r"(dst), "l"(src))
#define CP_COMMIT() asm volatile("cp.async.commit_group;")
#define CP_WAIT(n)  asm volatile("cp.async.wait_group %0;" :: "n"(n))

// ---------------- fused LN + QKVG GEMM + bias projection -----------------------
// One block = 128 input rows. LayerNorm computed in-flight while staging the
// fp16 A tile (2 threads per row, stats pass + normalize pass); bias_h (z@Wb,
// x LOG2E, fp16, transposed) computed from the same fp32 z values. Then 4
// weight GEMMs (double-buffered), epilogue stores fp16 transposed.
struct FusedArgs {
    const float* pair;
    const float* gamma;
    const float* beta;
    const float* W[4];
    __half*      out[4];
    const float* bias[4];
    float        oscale[4];
    int          sig[4];
    const float* Wb;
    __half*      bias_h;
};

#define HGEMM_SMEM (3 * 17408 * 2)   // 104448 bytes

__global__ void __launch_bounds__(256, 2)
fused_qkvg_kernel(FusedArgs fa) {
    extern __shared__ __half hsm[];
    __half* Ah = hsm;                 // 128 * 136
    __half* Bbuf0 = hsm + 17408;
    __half* Bbuf1 = hsm + 34816;
    const int t = threadIdx.x;
    const int lane = t & 31, warp = t >> 5;
    const int wm = warp & 3, wn = warp >> 2;
    const int m0w = wm * 32, n0w = wn * 64;
    const int g = lane >> 2, q = lane & 3;
    const int row0 = blockIdx.x * 128;

    // ---- LN pass 1: stats (2 threads per row, 64 channels each) ----
    const int arow = t >> 1, ahalf = t & 1;
    const float4* prow = (const float4*)(fa.pair + (size_t)(row0 + arow) * CC + ahalf * 64);
    float s = 0.f, sq = 0.f;
    #pragma unroll
    for (int i = 0; i < 16; i++) {
        float4 v = prow[i];
        s  += v.x + v.y + v.z + v.w;
        sq += v.x*v.x + v.y*v.y + v.z*v.z + v.w*v.w;
    }
    s  += __shfl_xor_sync(0xffffffffu, s,  1);
    sq += __shfl_xor_sync(0xffffffffu, sq, 1);
    const float mu = s * (1.0f / CC);
    const float rs = rsqrtf(sq * (1.0f / CC) - mu * mu + LN_EPS);

    // ---- LN pass 2: normalize, store fp16 A tile, accumulate bias dots ----
    const float4* gam4 = (const float4*)(fa.gamma + ahalf * 64);
    const float4* bet4 = (const float4*)(fa.beta  + ahalf * 64);
    const float4* Wb4  = (const float4*)fa.Wb;
    float4 bacc = make_float4(0.f, 0.f, 0.f, 0.f);
    #pragma unroll
    for (int i = 0; i < 16; i++) {
        float4 v = prow[i];
        float4 g4 = gam4[i];
        float4 b4 = bet4[i];
        float z0 = (v.x - mu) * rs * g4.x + b4.x;
        float z1 = (v.y - mu) * rs * g4.y + b4.y;
        float z2 = (v.z - mu) * rs * g4.z + b4.z;
        float z3 = (v.w - mu) * rs * g4.w + b4.w;
        int c0 = ahalf * 64 + i * 4;
        uint2 p;
        p.x = f16x2(z1, z0);
        p.y = f16x2(z3, z2);
        *(uint2*)(Ah + arow * 136 + c0) = p;
        float4 w0 = Wb4[c0], w1 = Wb4[c0 + 1], w2 = Wb4[c0 + 2], w3 = Wb4[c0 + 3];
        bacc.x += z0*w0.x + z1*w1.x + z2*w2.x + z3*w3.x;
        bacc.y += z0*w0.y + z1*w1.y + z2*w2.y + z3*w3.y;
        bacc.z += z0*w0.z + z1*w1.z + z2*w2.z + z3*w3.z;
        bacc.w += z0*w0.w + z1*w1.w + z2*w2.w + z3*w3.w;
    }
    bacc.x += __shfl_xor_sync(0xffffffffu, bacc.x, 1);
    bacc.y += __shfl_xor_sync(0xffffffffu, bacc.y, 1);
    bacc.z += __shfl_xor_sync(0xffffffffu, bacc.z, 1);
    bacc.w += __shfl_xor_sync(0xffffffffu, bacc.w, 1);
    if (ahalf == 0) {
        int R = row0 + arow;
        int o = ((R & 255) << 8) | (R >> 8);   // bias_t[n][j][i]
        fa.bias_h[0 * MTOT + o] = __float2half(bacc.x * LOG2E);
        fa.bias_h[1 * MTOT + o] = __float2half(bacc.y * LOG2E);
        fa.bias_h[2 * MTOT + o] = __float2half(bacc.z * LOG2E);
        fa.bias_h[3 * MTOT + o] = __float2half(bacc.w * LOG2E);
    }

    // ---- stage W[0] ----
    {
        const float* W = fa.W[0];
        #pragma unroll
        for (int i = 0; i < 16; i++) {
            int id = t + i * 256;
            int kk = id >> 5, n4 = id & 31;
            float4 v = ((const float4*)W)[(size_t)kk * 32 + n4];
            uint2 p;
            p.x = f16x2(v.y, v.x);
            p.y = f16x2(v.w, v.z);
            *(uint2*)(Bbuf0 + kk * 136 + n4 * 4) = p;
        }
    }
    __syncthreads();

    uint32_t aBase[2];
    #pragma unroll
    for (int mt = 0; mt < 2; mt++)
        aBase[mt] = (uint32_t)__cvta_generic_to_shared(
            Ah + (m0w + 16 * mt + (lane & 15)) * 136 + (lane >> 4) * 8);
    const int krow_l = (lane & 7) + (((lane & 15) >> 3) << 3);
    const int ncol_l = (lane >> 4) * 8;
    uint32_t bBase[2];
    bBase[0] = (uint32_t)__cvta_generic_to_shared(Bbuf0 + krow_l * 136 + n0w + ncol_l);
    bBase[1] = (uint32_t)__cvta_generic_to_shared(Bbuf1 + krow_l * 136 + n0w + ncol_l);

    for (int w = 0; w < 4; w++) {
        if (w + 1 < 4) {
            __half* Bn = ((w + 1) & 1) ? Bbuf1 : Bbuf0;
            const float* W = fa.W[w + 1];
            #pragma unroll
            for (int i = 0; i < 16; i++) {
                int id = t + i * 256;
                int kk = id >> 5, n4 = id & 31;
                float4 v = ((const float4*)W)[(size_t)kk * 32 + n4];
                uint2 p;
                p.x = f16x2(v.y, v.x);
                p.y = f16x2(v.w, v.z);
                *(uint2*)(Bn + kk * 136 + n4 * 4) = p;
            }
        }

        float4 acc[2][8];
        #pragma unroll
        for (int mt = 0; mt < 2; mt++)
            #pragma unroll
            for (int nt = 0; nt < 8; nt++) acc[mt][nt] = make_float4(0.f, 0.f, 0.f, 0.f);

        const uint32_t bB = bBase[w & 1];
        #pragma unroll
        for (int step = 0; step < 8; step++) {
            uint32_t a0[4], a1[4];
            LDSM_X4(a0[0], a0[1], a0[2], a0[3], aBase[0] + step * 32);
            LDSM_X4(a1[0], a1[1], a1[2], a1[3], aBase[1] + step * 32);
            #pragma unroll
            for (int p2 = 0; p2 < 4; p2++) {
                uint32_t b0, b1, b2, b3;
                LDSM_X4_T(b0, b1, b2, b3, bB + (step * 2176 + p2 * 16) * 2);
                mma_f16(acc[0][2*p2],   a0[0], a0[1], a0[2], a0[3], b0, b1);
                mma_f16(acc[0][2*p2+1], a0[0], a0[1], a0[2], a0[3], b2, b3);
                mma_f16(acc[1][2*p2],   a1[0], a1[1], a1[2], a1[3], b0, b1);
                mma_f16(acc[1][2*p2+1], a1[0], a1[1], a1[2], a1[3], b2, b3);
            }
        }

        const float* bias = fa.bias[w];
        const int sig = fa.sig[w];
        const float osc = fa.oscale[w];
        __half* o = fa.out[w];
        float2 bv[8];
        #pragma unroll
        for (int nt = 0; nt < 8; nt++) {
            if (bias) bv[nt] = *(const float2*)(bias + n0w + nt * 8 + 2 * q);
            else      bv[nt] = make_float2(0.f, 0.f);
        }
        #pragma unroll
        for (int mt = 0; mt < 2; mt++) {
            int r  = row0 + m0w + mt * 16 + g;
            int r2 = r + 8;
            int or0 = ((r  & 255) << 8) | (r  >> 8);
            int or1 = ((r2 & 255) << 8) | (r2 >> 8);
            #pragma unroll
            for (int nt = 0; nt < 8; nt++) {
                int col = n0w + nt * 8 + 2 * q;
                float4 c = acc[mt][nt];
                float v0 = (c.x + bv[nt].x) * osc, v1 = (c.y + bv[nt].y) * osc;
                float v2 = (c.z + bv[nt].x) * osc, v3 = (c.w + bv[nt].y) * osc;
                if (sig) {
                    v0 = 1.0f / (1.0f + __expf(-v0));
                    v1 = 1.0f / (1.0f + __expf(-v1));
                    v2 = 1.0f / (1.0f + __expf(-v2));
                    v3 = 1.0f / (1.0f + __expf(-v3));
                }
                *(uint32_t*)(o + (size_t)or0 * CC + col) = f16x2(v1, v0);
                *(uint32_t*)(o + (size_t)or1 * CC + col) = f16x2(v3, v2);
            }
        }
        __syncthreads();
    }
}

// ---------------- out-projection GEMM: og fp32 -> out fp32 ---------------------
struct GemmArgs {
    const float* A;
    const float* W;
    float*       out;
    const float* bias;
};

__global__ void __launch_bounds__(256, 2)
hgemm_out_kernel(GemmArgs ga) {
    extern __shared__ __half hsm[];
    __half* Ah = hsm;
    __half* Bbuf0 = hsm + 17408;
    const int t = threadIdx.x;
    const int lane = t & 31, warp = t >> 5;
    const int wm = warp & 3, wn = warp >> 2;
    const int m0w = wm * 32, n0w = wn * 64;
    const int g = lane >> 2, q = lane & 3;
    const int row0 = blockIdx.x * 128;

    #pragma unroll
    for (int i = 0; i < 16; i++) {
        int id = t + i * 256;
        int r = id >> 5, c = id & 31;
        float4 v = ((const float4*)ga.A)[(size_t)(row0 + r) * 32 + c];
        uint2 p;
        p.x = f16x2(v.y, v.x);
        p.y = f16x2(v.w, v.z);
        *(uint2*)(Ah + r * 136 + c * 4) = p;
    }
    #pragma unroll
    for (int i = 0; i < 16; i++) {
        int id = t + i * 256;
        int kk = id >> 5, n4 = id & 31;
        float4 v = ((const float4*)ga.W)[(size_t)kk * 32 + n4];
        uint2 p;
        p.x = f16x2(v.y, v.x);
        p.y = f16x2(v.w, v.z);
        *(uint2*)(Bbuf0 + kk * 136 + n4 * 4) = p;
    }
    __syncthreads();

    uint32_t aBase[2];
    #pragma unroll
    for (int mt = 0; mt < 2; mt++)
        aBase[mt] = (uint32_t)__cvta_generic_to_shared(
            Ah + (m0w + 16 * mt + (lane & 15)) * 136 + (lane >> 4) * 8);
    const int krow_l = (lane & 7) + (((lane & 15) >> 3) << 3);
    const int ncol_l = (lane >> 4) * 8;
    const uint32_t bB = (uint32_t)__cvta_generic_to_shared(Bbuf0 + krow_l * 136 + n0w + ncol_l);

    float4 acc[2][8];
    #pragma unroll
    for (int mt = 0; mt < 2; mt++)
        #pragma unroll
        for (int nt = 0; nt < 8; nt++) acc[mt][nt] = make_float4(0.f, 0.f, 0.f, 0.f);

    #pragma unroll
    for (int step = 0; step < 8; step++) {
        uint32_t a0[4], a1[4];
        LDSM_X4(a0[0], a0[1], a0[2], a0[3], aBase[0] + step * 32);
        LDSM_X4(a1[0], a1[1], a1[2], a1[3], aBase[1] + step * 32);
        #pragma unroll
        for (int p2 = 0; p2 < 4; p2++) {
            uint32_t b0, b1, b2, b3;
            LDSM_X4_T(b0, b1, b2, b3, bB + (step * 2176 + p2 * 16) * 2);
            mma_f16(acc[0][2*p2],   a0[0], a0[1], a0[2], a0[3], b0, b1);
            mma_f16(acc[0][2*p2+1], a0[0], a0[1], a0[2], a0[3], b2, b3);
            mma_f16(acc[1][2*p2],   a1[0], a1[1], a1[2], a1[3], b0, b1);
            mma_f16(acc[1][2*p2+1], a1[0], a1[1], a1[2], a1[3], b2, b3);
        }
    }

    float2 bv[8];
    #pragma unroll
    for (int nt = 0; nt < 8; nt++)
        bv[nt] = *(const float2*)(ga.bias + n0w + nt * 8 + 2 * q);
    #pragma unroll
    for (int mt = 0; mt < 2; mt++) {
        int r  = row0 + m0w + mt * 16 + g;
        int r2 = r + 8;
        int or0 = ((r  & 255) << 8) | (r  >> 8);
        int or1 = ((r2 & 255) << 8) | (r2 >> 8);
        #pragma unroll
        for (int nt = 0; nt < 8; nt++) {
            int col = n0w + nt * 8 + 2 * q;
            float4 c = acc[mt][nt];
            *(float2*)(ga.out + (size_t)or0 * CC + col) =
                make_float2(c.x + bv[nt].x, c.y + bv[nt].y);
            *(float2*)(ga.out + (size_t)or1 * CC + col) =
                make_float2(c.z + bv[nt].x, c.w + bv[nt].y);
        }
    }
}

// ---------------- all-fp16 MMA flash attention ---------------------------------
// 128-thread CTAs (4 warps x 32 query rows), 2 CTAs/SM; grid (j, ih=2, n).
#define ATT_SMEM_BYTES (27648 * 2)   // 55296 bytes
__global__ void __launch_bounds__(128, 2)
attn_mma_kernel(const __half* __restrict__ qt, const __half* __restrict__ kt,
                const __half* __restrict__ vt, const __half* __restrict__ gt,
                const __half* __restrict__ bias_h, float* __restrict__ og) {
    extern __shared__ __half hsm2[];
    const uint32_t smemB = (uint32_t)__cvta_generic_to_shared(hsm2);

    const int j = blockIdx.x, ih = blockIdx.y, n = blockIdx.z;
    const int t = threadIdx.x;
    const int lane = t & 31, w = t >> 5;
    const int g = lane >> 2, q = lane & 3;
    const int I0 = ih * 128 + w * 32;

    uint32_t qa[2][2][4];
    #pragma unroll
    for (int mt = 0; mt < 2; mt++) {
        const __half* qp0 = qt + (size_t)(j * SS + I0 + mt * 16 + g) * CC + n * HD;
        const __half* qp1 = qp0 + 8 * CC;
        #pragma unroll
        for (int kt2 = 0; kt2 < 2; kt2++) {
            qa[mt][kt2][0] = *(const uint32_t*)(qp0 + kt2 * 16 + 2 * q);
            qa[mt][kt2][1] = *(const uint32_t*)(qp1 + kt2 * 16 + 2 * q);
            qa[mt][kt2][2] = *(const uint32_t*)(qp0 + kt2 * 16 + 8 + 2 * q);
            qa[mt][kt2][3] = *(const uint32_t*)(qp1 + kt2 * 16 + 8 + 2 * q);
        }
    }

    const int koff = ((lane & 7) + ((lane >> 4) << 3)) * 40 + (((lane >> 3) & 1) << 3);
    const int voff = ((lane & 7) + (((lane >> 3) & 1) << 3)) * 40 + ((lane >> 4) << 3);
    const size_t kvbase = (size_t)(j * SS) * CC + n * HD;

    float m_[2][2], l_[2][2];
    float4 o_[2][4];
    #pragma unroll
    for (int mt = 0; mt < 2; mt++) {
        m_[mt][0] = m_[mt][1] = -1e30f;
        l_[mt][0] = l_[mt][1] = 0.f;
        #pragma unroll
        for (int nt = 0; nt < 4; nt++) o_[mt][nt] = make_float4(0.f, 0.f, 0.f, 0.f);
    }

    auto stage = [&](int c, int buf) {
        #pragma unroll
        for (int i = 0; i < 2; i++) {
            int id = t + i * 128;
            int row = id >> 2, seg = id & 3;
            uint32_t kdst = smemB + (buf * 2560 + row * 40 + seg * 8) * 2;
            CP_ASYNC16(kdst, kt + kvbase + (size_t)(c * 64 + row) * CC + seg * 8);
            uint32_t vdst = smemB + ((5120 + buf * 2560) + row * 40 + seg * 8) * 2;
            CP_ASYNC16(vdst, vt + kvbase + (size_t)(c * 64 + row) * CC + seg * 8);
        }
        #pragma unroll
        for (int i = 0; i < 8; i++) {
            int id = t + i * 128;
            int brow = id >> 4, bseg = id & 15;
            uint32_t bdst = smemB + ((10240 + buf * 8704) + brow * 136 + bseg * 8) * 2;
            CP_ASYNC16(bdst, bias_h + (size_t)n * MTOT +
                             (size_t)(c * 64 + brow) * SS + ih * 128 + bseg * 8);
        }
    };

    stage(0, 0); CP_COMMIT();
    stage(1, 1); CP_COMMIT();

    for (int c = 0; c < 4; c++) {
        const int buf = c & 1;
        if (c < 3) { CP_WAIT(1); } else { CP_WAIT(0); }
        __syncthreads();

        const uint32_t kB = smemB + (buf * 2560 + koff) * 2;
        const uint32_t vB = smemB + ((5120 + buf * 2560) + voff) * 2;
        const __half* Bsl = hsm2 + 10240 + buf * 8704;

        float4 sc[2][8];
        #pragma unroll
        for (int mt = 0; mt < 2; mt++) {
            int i0l = w * 32 + mt * 16 + g;
            #pragma unroll
            for (int nt = 0; nt < 8; nt++) {
                int kl = nt * 8 + 2 * q;
                const __half* b0p = Bsl + kl * 136 + i0l;
                const __half* b1p = b0p + 136;
                sc[mt][nt].x = __half2float(b0p[0]);
                sc[mt][nt].y = __half2float(b1p[0]);
                sc[mt][nt].z = __half2float(b0p[8]);
                sc[mt][nt].w = __half2float(b1p[8]);
            }
        }

        #pragma unroll
        for (int kt2 = 0; kt2 < 2; kt2++) {
            #pragma unroll
            for (int ntp = 0; ntp < 4; ntp++) {
                uint32_t b0, b1, b2, b3;
                LDSM_X4(b0, b1, b2, b3, kB + (ntp * 640 + kt2 * 16) * 2);
                mma_f16(sc[0][2*ntp],   qa[0][kt2][0], qa[0][kt2][1], qa[0][kt2][2], qa[0][kt2][3], b0, b1);
                mma_f16(sc[0][2*ntp+1], qa[0][kt2][0], qa[0][kt2][1], qa[0][kt2][2], qa[0][kt2][3], b2, b3);
                mma_f16(sc[1][2*ntp],   qa[1][kt2][0], qa[1][kt2][1], qa[1][kt2][2], qa[1][kt2][3], b0, b1);
                mma_f16(sc[1][2*ntp+1], qa[1][kt2][0], qa[1][kt2][1], qa[1][kt2][2], qa[1][kt2][3], b2, b3);
            }
        }

        float mx[2][2] = {{-1e30f, -1e30f}, {-1e30f, -1e30f}};
        #pragma unroll
        for (int mt = 0; mt < 2; mt++)
            #pragma unroll
            for (int nt = 0; nt < 8; nt++) {
                float4 s = sc[mt][nt];
                mx[mt][0] = fmaxf(mx[mt][0], fmaxf(s.x, s.y));
                mx[mt][1] = fmaxf(mx[mt][1], fmaxf(s.z, s.w));
            }
        #pragma unroll
        for (int mt = 0; mt < 2; mt++)
            #pragma unroll
            for (int h = 0; h < 2; h++) {
                float v = mx[mt][h];
                v = fmaxf(v, __shfl_xor_sync(0xffffffffu, v, 1));
                v = fmaxf(v, __shfl_xor_sync(0xffffffffu, v, 2));
                mx[mt][h] = v;
            }

        float al[2][2], mn[2][2];
        #pragma unroll
        for (int mt = 0; mt < 2; mt++)
            #pragma unroll
            for (int h = 0; h < 2; h++) {
                mn[mt][h] = fmaxf(m_[mt][h], mx[mt][h]);
                al[mt][h] = fexp2(m_[mt][h] - mn[mt][h]);
                m_[mt][h] = mn[mt][h];
            }

        float rs_[2][2] = {{0.f, 0.f}, {0.f, 0.f}};
        #pragma unroll
        for (int mt = 0; mt < 2; mt++) {
            #pragma unroll
            for (int nt = 0; nt < 8; nt++) {
                float4 s = sc[mt][nt];
                s.x = fexp2(s.x - mn[mt][0]);
                s.y = fexp2(s.y - mn[mt][0]);
                s.z = fexp2(s.z - mn[mt][1]);
                s.w = fexp2(s.w - mn[mt][1]);
                sc[mt][nt] = s;
                rs_[mt][0] += s.x + s.y;
                rs_[mt][1] += s.z + s.w;
            }
        }
        #pragma unroll
        for (int mt = 0; mt < 2; mt++)
            #pragma unroll
            for (int h = 0; h < 2; h++) {
                float v = rs_[mt][h];
                v += __shfl_xor_sync(0xffffffffu, v, 1);
                v += __shfl_xor_sync(0xffffffffu, v, 2);
                l_[mt][h] = fmaf(l_[mt][h], al[mt][h], v);
            }

        #pragma unroll
        for (int mt = 0; mt < 2; mt++)
            #pragma unroll
            for (int nt = 0; nt < 4; nt++) {
                o_[mt][nt].x *= al[mt][0];
                o_[mt][nt].y *= al[mt][0];
                o_[mt][nt].z *= al[mt][1];
                o_[mt][nt].w *= al[mt][1];
            }

        #pragma unroll
        for (int kt2 = 0; kt2 < 4; kt2++) {
            uint32_t pa[2][4];
            #pragma unroll
            for (int mt = 0; mt < 2; mt++) {
                float4 p0 = sc[mt][2 * kt2];
                float4 p1 = sc[mt][2 * kt2 + 1];
                pa[mt][0] = f16x2(p0.y, p0.x);
                pa[mt][1] = f16x2(p0.w, p0.z);
                pa[mt][2] = f16x2(p1.y, p1.x);
                pa[mt][3] = f16x2(p1.w, p1.z);
            }
            #pragma unroll
            for (int db = 0; db < 2; db++) {
                uint32_t b0, b1, b2, b3;
                LDSM_X4_T(b0, b1, b2, b3, vB + (kt2 * 640 + db * 16) * 2);
                mma_f16(o_[0][2*db],   pa[0][0], pa[0][1], pa[0][2], pa[0][3], b0, b1);
                mma_f16(o_[0][2*db+1], pa[0][0], pa[0][1], pa[0][2], pa[0][3], b2, b3);
                mma_f16(o_[1][2*db],   pa[1][0], pa[1][1], pa[1][2], pa[1][3], b0, b1);
                mma_f16(o_[1][2*db+1], pa[1][0], pa[1][1], pa[1][2], pa[1][3], b2, b3);
            }
        }

        __syncthreads();
        if (c + 2 < 4) { stage(c + 2, buf); CP_COMMIT(); }
    }

    #pragma unroll
    for (int mt = 0; mt < 2; mt++) {
        float i0v = 1.f / l_[mt][0];
        float i1v = 1.f / l_[mt][1];
        size_t r0 = (size_t)(j * SS + I0 + mt * 16 + g) * CC + n * HD;
        size_t r1 = r0 + 8 * CC;
        #pragma unroll
        for (int nt2 = 0; nt2 < 4; nt2++) {
            int col = nt2 * 8 + 2 * q;
            float2 g0 = __half22float2(*(const __half2*)(gt + r0 + col));
            float2 g1 = __half22float2(*(const __half2*)(gt + r1 + col));
            float4 o4 = o_[mt][nt2];
            *(float2*)(og + r0 + col) = make_float2(o4.x * i0v * g0.x, o4.y * i0v * g0.y);
            *(float2*)(og + r1 + col) = make_float2(o4.z * i1v * g1.x, o4.w * i1v * g1.y);
        }
    }
}

// ---------------- launch -------------------------------------------------------
extern "C" void kernel_launch(void* const* d_in, const int* in_sizes, int n_in,
                              void* d_out, int out_size) {
    const float* pair  = (const float*)d_in[0];
    const float* gamma = (const float*)d_in[1];
    const float* beta  = (const float*)d_in[2];
    const float* Wq    = (const float*)d_in[3];
    const float* Wk    = (const float*)d_in[4];
    const float* Wv    = (const float*)d_in[5];
    const float* Wb    = (const float*)d_in[6];
    const float* Wg    = (const float*)d_in[7];
    const float* bg    = (const float*)d_in[8];
    const float* Wo    = (const float*)d_in[9];
    const float* bo    = (const float*)d_in[10];
    float* out = (float*)d_out;

    float* base = nullptr;
    cudaGetSymbolAddress((void**)&base, g_scratch);
    __half* qt     = (__half*)(base);
    __half* kt     = (__half*)(base + 4194304);
    __half* vt     = (__half*)(base + 8388608);
    __half* gt     = (__half*)(base + 12582912);
    float*  og     = base + 16777216;
    __half* bias_h = (__half*)(base + 25165824);

    cudaFuncSetAttribute(fused_qkvg_kernel,
                         cudaFuncAttributeMaxDynamicSharedMemorySize, HGEMM_SMEM);
    cudaFuncSetAttribute(hgemm_out_kernel,
                         cudaFuncAttributeMaxDynamicSharedMemorySize, HGEMM_SMEM);
    cudaFuncSetAttribute(attn_mma_kernel,
                         cudaFuncAttributeMaxDynamicSharedMemorySize, ATT_SMEM_BYTES);

    FusedArgs fa;
    fa.pair = pair; fa.gamma = gamma; fa.beta = beta;
    fa.W[0] = Wq; fa.W[1] = Wk; fa.W[2] = Wv; fa.W[3] = Wg;
    fa.out[0] = qt; fa.out[1] = kt; fa.out[2] = vt; fa.out[3] = gt;
    fa.bias[0] = nullptr; fa.bias[1] = nullptr; fa.bias[2] = nullptr; fa.bias[3] = bg;
    fa.oscale[0] = ATT_SCALE * LOG2E; fa.oscale[1] = 1.f; fa.oscale[2] = 1.f; fa.oscale[3] = 1.f;
    fa.sig[0] = 0; fa.sig[1] = 0; fa.sig[2] = 0; fa.sig[3] = 1;
    fa.Wb = Wb; fa.bias_h = bias_h;
    fused_qkvg_kernel<<<MTOT / 128, 256, HGEMM_SMEM>>>(fa);

    attn_mma_kernel<<<dim3(SS, 2, NH), 128, ATT_SMEM_BYTES>>>(qt, kt, vt, gt, bias_h, og);

    GemmArgs oa;
    oa.A = og;
    oa.W = Wo;
    oa.out = out;
    oa.bias = bo;
    hgemm_out_kernel<<<MTOT / 128, 256, HGEMM_SMEM>>>(oa);
}

// round 15
// speedup vs baseline: 2.1687x; 1.0673x over previous
#include <cuda_runtime.h>
#include <cuda_fp16.h>
#include <math.h>
#include <stdint.h>

#define SS 256       // sequence
#define CC 128       // channels
#define NH 4
#define HD 32
#define MTOT (SS*SS) // 65536
#define ATT_SCALE 0.17677669529663687f  // 1/sqrt(32)
#define LOG2E 1.4426950408889634f
#define LN_EPS 1e-5f

// ---------------- scratch (offsets in floats) ----------------------------------
//   qt   : [0,        4194304)   fp16 (8388608 halves), row = j*S + i (pre-scaled ATT_SCALE*LOG2E)
//   kt   : [4194304,  8388608)   fp16
//   vt   : [8388608, 12582912)   fp16
//   gt   : [12582912,16777216)   fp16
//   og   : [16777216,20971520)   fp16 gated attention output
//   bias : [20971520,21102592)   fp16 [n][k][i] (NH*MTOT = 262144 halves), x LOG2E
//   w16  : [21102592,21143552)   fp16 weights: Wq,Wk,Wv,Wg,Wo (16384 halves each)
__device__ float g_scratch[21143552];

__device__ __forceinline__ float fexp2(float x) {
    float r;
    asm("ex2.approx.ftz.f32 %0, %1;" : "=f"(r) : "f"(x));
    return r;
}

// pack two fp32 -> f16x2 (lo = second operand) — empirically validated in R8/R9.
__device__ __forceinline__ uint32_t f16x2(float hi, float lo) {
    uint32_t r;
    asm("cvt.rn.f16x2.f32 %0, %1, %2;" : "=r"(r) : "f"(hi), "f"(lo));
    return r;
}

__device__ __forceinline__ void mma_f16(float4& c, uint32_t a0, uint32_t a1,
                                        uint32_t a2, uint32_t a3,
                                        uint32_t b0, uint32_t b1) {
    asm volatile(
        "mma.sync.aligned.m16n8k16.row.col.f32.f16.f16.f32 "
        "{%0,%1,%2,%3}, {%4,%5,%6,%7}, {%8,%9}, {%0,%1,%2,%3};"
        : "+f"(c.x), "+f"(c.y), "+f"(c.z), "+f"(c.w)
        : "r"(a0), "r"(a1), "r"(a2), "r"(a3), "r"(b0), "r"(b1));
}

#define LDSM_X4(d0,d1,d2,d3,a) \
    asm volatile("ldmatrix.sync.aligned.m8n8.x4.shared.b16 {%0,%1,%2,%3}, [%4];" \
                 : "=r"(d0),"=r"(d1),"=r"(d2),"=r"(d3) : "r"(a))
#define LDSM_X4_T(d0,d1,d2,d3,a) \
    asm volatile("ldmatrix.sync.aligned.m8n8.x4.trans.shared.b16 {%0,%1,%2,%3}, [%4];" \
                 : "=r"(d0),"=r"(d1),"=r"(d2),"=r"(d3) : "r"(a))

#define CP_ASYNC16(dst, src) \
    asm volatile("cp.async.ca.shared.global [%0], [%1], 16;" :: "r"(dst), "l"(src))
#define CP_COMMIT() asm volatile("cp.async.commit_group;")
#define CP_WAIT(n)  asm volatile("cp.async.wait_group %0;" :: "n"(n))

// ---------------- weight conversion: 5 x [128,128] fp32 -> fp16 ----------------
__global__ void wconv_kernel(const float* __restrict__ Wq, const float* __restrict__ Wk,
                             const float* __restrict__ Wv, const float* __restrict__ Wg,
                             const float* __restrict__ Wo, __half* __restrict__ dst) {
    int id = blockIdx.x * 256 + threadIdx.x;      // 0..20479 float4s
    const float* srcs[5] = {Wq, Wk, Wv, Wg, Wo};
    int wsel = id >> 12, off = id & 4095;
    float4 v = ((const float4*)srcs[wsel])[off];
    uint2 p;
    p.x = f16x2(v.y, v.x);
    p.y = f16x2(v.w, v.z);
    *(uint2*)(dst + wsel * 16384 + off * 4) = p;
}

// ---------------- fused LN + QKVG GEMM + bias projection -----------------------
// One block = 128 input rows. LN computed in-flight while staging the fp16 A
// tile; bias_h (z@Wb x LOG2E) from the same fp32 z values. Weights (fp16,
// pre-converted) staged via cp.async double-buffered pipeline.
struct FusedArgs {
    const float*  pair;
    const float*  gamma;
    const float*  beta;
    const __half* W16[4];
    __half*       out[4];
    const float*  bias[4];
    float         oscale[4];
    int           sig[4];
    const float*  Wb;
    __half*       bias_h;
};

#define HGEMM_SMEM (3 * 17408 * 2)   // 104448 bytes

__global__ void __launch_bounds__(256, 2)
fused_qkvg_kernel(FusedArgs fa) {
    extern __shared__ __half hsm[];
    __half* Ah = hsm;                 // 128 * 136
    __half* Bbuf0 = hsm + 17408;
    __half* Bbuf1 = hsm + 34816;
    const uint32_t b0B = (uint32_t)__cvta_generic_to_shared(Bbuf0);
    const uint32_t b1B = (uint32_t)__cvta_generic_to_shared(Bbuf1);
    const int t = threadIdx.x;
    const int lane = t & 31, warp = t >> 5;
    const int wm = warp & 3, wn = warp >> 2;
    const int m0w = wm * 32, n0w = wn * 64;
    const int g = lane >> 2, q = lane & 3;
    const int row0 = blockIdx.x * 128;

    // ---- async-stage weight w into buffer buf (fp16 src, raw 16B copies) ----
    auto stageW = [&](int w, int buf) {
        const __half* W = fa.W16[w];
        const uint32_t dstB = buf ? b1B : b0B;
        #pragma unroll
        for (int i = 0; i < 8; i++) {
            int id = t + i * 256;            // 0..2047 16B chunks
            int kk = id >> 4, seg = id & 15;
            CP_ASYNC16(dstB + (kk * 136 + seg * 8) * 2, W + kk * 128 + seg * 8);
        }
    };
    stageW(0, 0); CP_COMMIT();

    // ---- LN pass 1: stats (2 threads per row, 64 channels each) ----
    const int arow = t >> 1, ahalf = t & 1;
    const float4* prow = (const float4*)(fa.pair + (size_t)(row0 + arow) * CC + ahalf * 64);
    float s = 0.f, sq = 0.f;
    #pragma unroll
    for (int i = 0; i < 16; i++) {
        float4 v = prow[i];
        s  += v.x + v.y + v.z + v.w;
        sq += v.x*v.x + v.y*v.y + v.z*v.z + v.w*v.w;
    }
    s  += __shfl_xor_sync(0xffffffffu, s,  1);
    sq += __shfl_xor_sync(0xffffffffu, sq, 1);
    const float mu = s * (1.0f / CC);
    const float rs = rsqrtf(sq * (1.0f / CC) - mu * mu + LN_EPS);

    // ---- LN pass 2: normalize, store fp16 A tile, accumulate bias dots ----
    const float4* gam4 = (const float4*)(fa.gamma + ahalf * 64);
    const float4* bet4 = (const float4*)(fa.beta  + ahalf * 64);
    const float4* Wb4  = (const float4*)fa.Wb;
    float4 bacc = make_float4(0.f, 0.f, 0.f, 0.f);
    #pragma unroll
    for (int i = 0; i < 16; i++) {
        float4 v = prow[i];
        float4 g4 = gam4[i];
        float4 b4 = bet4[i];
        float z0 = (v.x - mu) * rs * g4.x + b4.x;
        float z1 = (v.y - mu) * rs * g4.y + b4.y;
        float z2 = (v.z - mu) * rs * g4.z + b4.z;
        float z3 = (v.w - mu) * rs * g4.w + b4.w;
        int c0 = ahalf * 64 + i * 4;
        uint2 p;
        p.x = f16x2(z1, z0);
        p.y = f16x2(z3, z2);
        *(uint2*)(Ah + arow * 136 + c0) = p;
        float4 w0 = Wb4[c0], w1 = Wb4[c0 + 1], w2 = Wb4[c0 + 2], w3 = Wb4[c0 + 3];
        bacc.x += z0*w0.x + z1*w1.x + z2*w2.x + z3*w3.x;
        bacc.y += z0*w0.y + z1*w1.y + z2*w2.y + z3*w3.y;
        bacc.z += z0*w0.z + z1*w1.z + z2*w2.z + z3*w3.z;
        bacc.w += z0*w0.w + z1*w1.w + z2*w2.w + z3*w3.w;
    }
    bacc.x += __shfl_xor_sync(0xffffffffu, bacc.x, 1);
    bacc.y += __shfl_xor_sync(0xffffffffu, bacc.y, 1);
    bacc.z += __shfl_xor_sync(0xffffffffu, bacc.z, 1);
    bacc.w += __shfl_xor_sync(0xffffffffu, bacc.w, 1);
    if (ahalf == 0) {
        int R = row0 + arow;
        int o = ((R & 255) << 8) | (R >> 8);   // bias_t[n][j][i]
        fa.bias_h[0 * MTOT + o] = __float2half(bacc.x * LOG2E);
        fa.bias_h[1 * MTOT + o] = __float2half(bacc.y * LOG2E);
        fa.bias_h[2 * MTOT + o] = __float2half(bacc.z * LOG2E);
        fa.bias_h[3 * MTOT + o] = __float2half(bacc.w * LOG2E);
    }

    uint32_t aBase[2];
    #pragma unroll
    for (int mt = 0; mt < 2; mt++)
        aBase[mt] = (uint32_t)__cvta_generic_to_shared(
            Ah + (m0w + 16 * mt + (lane & 15)) * 136 + (lane >> 4) * 8);
    const int krow_l = (lane & 7) + (((lane & 15) >> 3) << 3);
    const int ncol_l = (lane >> 4) * 8;
    uint32_t bBase[2];
    bBase[0] = b0B + (krow_l * 136 + n0w + ncol_l) * 2;
    bBase[1] = b1B + (krow_l * 136 + n0w + ncol_l) * 2;

    for (int w = 0; w < 4; w++) {
        if (w < 3) { stageW(w + 1, (w + 1) & 1); CP_COMMIT(); }
        if (w < 3) { CP_WAIT(1); } else { CP_WAIT(0); }
        __syncthreads();

        float4 acc[2][8];
        #pragma unroll
        for (int mt = 0; mt < 2; mt++)
            #pragma unroll
            for (int nt = 0; nt < 8; nt++) acc[mt][nt] = make_float4(0.f, 0.f, 0.f, 0.f);

        const uint32_t bB = bBase[w & 1];
        #pragma unroll
        for (int step = 0; step < 8; step++) {
            uint32_t a0[4], a1[4];
            LDSM_X4(a0[0], a0[1], a0[2], a0[3], aBase[0] + step * 32);
            LDSM_X4(a1[0], a1[1], a1[2], a1[3], aBase[1] + step * 32);
            #pragma unroll
            for (int p2 = 0; p2 < 4; p2++) {
                uint32_t b0, b1, b2, b3;
                LDSM_X4_T(b0, b1, b2, b3, bB + (step * 2176 + p2 * 16) * 2);
                mma_f16(acc[0][2*p2],   a0[0], a0[1], a0[2], a0[3], b0, b1);
                mma_f16(acc[0][2*p2+1], a0[0], a0[1], a0[2], a0[3], b2, b3);
                mma_f16(acc[1][2*p2],   a1[0], a1[1], a1[2], a1[3], b0, b1);
                mma_f16(acc[1][2*p2+1], a1[0], a1[1], a1[2], a1[3], b2, b3);
            }
        }

        const float* bias = fa.bias[w];
        const int sig = fa.sig[w];
        const float osc = fa.oscale[w];
        __half* o = fa.out[w];
        float2 bv[8];
        #pragma unroll
        for (int nt = 0; nt < 8; nt++) {
            if (bias) bv[nt] = *(const float2*)(bias + n0w + nt * 8 + 2 * q);
            else      bv[nt] = make_float2(0.f, 0.f);
        }
        #pragma unroll
        for (int mt = 0; mt < 2; mt++) {
            int r  = row0 + m0w + mt * 16 + g;
            int r2 = r + 8;
            int or0 = ((r  & 255) << 8) | (r  >> 8);
            int or1 = ((r2 & 255) << 8) | (r2 >> 8);
            #pragma unroll
            for (int nt = 0; nt < 8; nt++) {
                int col = n0w + nt * 8 + 2 * q;
                float4 c = acc[mt][nt];
                float v0 = (c.x + bv[nt].x) * osc, v1 = (c.y + bv[nt].y) * osc;
                float v2 = (c.z + bv[nt].x) * osc, v3 = (c.w + bv[nt].y) * osc;
                if (sig) {
                    v0 = 1.0f / (1.0f + __expf(-v0));
                    v1 = 1.0f / (1.0f + __expf(-v1));
                    v2 = 1.0f / (1.0f + __expf(-v2));
                    v3 = 1.0f / (1.0f + __expf(-v3));
                }
                *(uint32_t*)(o + (size_t)or0 * CC + col) = f16x2(v1, v0);
                *(uint32_t*)(o + (size_t)or1 * CC + col) = f16x2(v3, v2);
            }
        }
        __syncthreads();
    }
}

// ---------------- out-projection GEMM: og fp16 -> out fp32 ---------------------
struct GemmArgs {
    const __half* A;     // og fp16
    const __half* W16;   // Wo fp16
    float*        out;
    const float*  bias;
};

__global__ void __launch_bounds__(256, 2)
hgemm_out_kernel(GemmArgs ga) {
    extern __shared__ __half hsm[];
    __half* Ah = hsm;
    __half* Bbuf0 = hsm + 17408;
    const uint32_t ahB = (uint32_t)__cvta_generic_to_shared(Ah);
    const uint32_t b0B = (uint32_t)__cvta_generic_to_shared(Bbuf0);
    const int t = threadIdx.x;
    const int lane = t & 31, warp = t >> 5;
    const int wm = warp & 3, wn = warp >> 2;
    const int m0w = wm * 32, n0w = wn * 64;
    const int g = lane >> 2, q = lane & 3;
    const int row0 = blockIdx.x * 128;

    #pragma unroll
    for (int i = 0; i < 8; i++) {
        int id = t + i * 256;            // 0..2047 16B chunks
        int r = id >> 4, seg = id & 15;
        CP_ASYNC16(ahB + (r * 136 + seg * 8) * 2, ga.A + (size_t)(row0 + r) * CC + seg * 8);
    }
    #pragma unroll
    for (int i = 0; i < 8; i++) {
        int id = t + i * 256;
        int kk = id >> 4, seg = id & 15;
        CP_ASYNC16(b0B + (kk * 136 + seg * 8) * 2, ga.W16 + kk * 128 + seg * 8);
    }
    CP_COMMIT(); CP_WAIT(0);
    __syncthreads();

    uint32_t aBase[2];
    #pragma unroll
    for (int mt = 0; mt < 2; mt++)
        aBase[mt] = ahB + ((m0w + 16 * mt + (lane & 15)) * 136 + (lane >> 4) * 8) * 2;
    const int krow_l = (lane & 7) + (((lane & 15) >> 3) << 3);
    const int ncol_l = (lane >> 4) * 8;
    const uint32_t bB = b0B + (krow_l * 136 + n0w + ncol_l) * 2;

    float4 acc[2][8];
    #pragma unroll
    for (int mt = 0; mt < 2; mt++)
        #pragma unroll
        for (int nt = 0; nt < 8; nt++) acc[mt][nt] = make_float4(0.f, 0.f, 0.f, 0.f);

    #pragma unroll
    for (int step = 0; step < 8; step++) {
        uint32_t a0[4], a1[4];
        LDSM_X4(a0[0], a0[1], a0[2], a0[3], aBase[0] + step * 32);
        LDSM_X4(a1[0], a1[1], a1[2], a1[3], aBase[1] + step * 32);
        #pragma unroll
        for (int p2 = 0; p2 < 4; p2++) {
            uint32_t b0, b1, b2, b3;
            LDSM_X4_T(b0, b1, b2, b3, bB + (step * 2176 + p2 * 16) * 2);
            mma_f16(acc[0][2*p2],   a0[0], a0[1], a0[2], a0[3], b0, b1);
            mma_f16(acc[0][2*p2+1], a0[0], a0[1], a0[2], a0[3], b2, b3);
            mma_f16(acc[1][2*p2],   a1[0], a1[1], a1[2], a1[3], b0, b1);
            mma_f16(acc[1][2*p2+1], a1[0], a1[1], a1[2], a1[3], b2, b3);
        }
    }

    float2 bv[8];
    #pragma unroll
    for (int nt = 0; nt < 8; nt++)
        bv[nt] = *(const float2*)(ga.bias + n0w + nt * 8 + 2 * q);
    #pragma unroll
    for (int mt = 0; mt < 2; mt++) {
        int r  = row0 + m0w + mt * 16 + g;
        int r2 = r + 8;
        int or0 = ((r  & 255) << 8) | (r  >> 8);
        int or1 = ((r2 & 255) << 8) | (r2 >> 8);
        #pragma unroll
        for (int nt = 0; nt < 8; nt++) {
            int col = n0w + nt * 8 + 2 * q;
            float4 c = acc[mt][nt];
            *(float2*)(ga.out + (size_t)or0 * CC + col) =
                make_float2(c.x + bv[nt].x, c.y + bv[nt].y);
            *(float2*)(ga.out + (size_t)or1 * CC + col) =
                make_float2(c.z + bv[nt].x, c.w + bv[nt].y);
        }
    }
}

// ---------------- all-fp16 MMA flash attention ---------------------------------
// 128-thread CTAs (4 warps x 32 query rows), 2 CTAs/SM; grid (j, ih=2, n).
#define ATT_SMEM_BYTES (27648 * 2)   // 55296 bytes
__global__ void __launch_bounds__(128, 2)
attn_mma_kernel(const __half* __restrict__ qt, const __half* __restrict__ kt,
                const __half* __restrict__ vt, const __half* __restrict__ gt,
                const __half* __restrict__ bias_h, __half* __restrict__ og) {
    extern __shared__ __half hsm2[];
    const uint32_t smemB = (uint32_t)__cvta_generic_to_shared(hsm2);

    const int j = blockIdx.x, ih = blockIdx.y, n = blockIdx.z;
    const int t = threadIdx.x;
    const int lane = t & 31, w = t >> 5;
    const int g = lane >> 2, q = lane & 3;
    const int I0 = ih * 128 + w * 32;

    uint32_t qa[2][2][4];
    #pragma unroll
    for (int mt = 0; mt < 2; mt++) {
        const __half* qp0 = qt + (size_t)(j * SS + I0 + mt * 16 + g) * CC + n * HD;
        const __half* qp1 = qp0 + 8 * CC;
        #pragma unroll
        for (int kt2 = 0; kt2 < 2; kt2++) {
            qa[mt][kt2][0] = *(const uint32_t*)(qp0 + kt2 * 16 + 2 * q);
            qa[mt][kt2][1] = *(const uint32_t*)(qp1 + kt2 * 16 + 2 * q);
            qa[mt][kt2][2] = *(const uint32_t*)(qp0 + kt2 * 16 + 8 + 2 * q);
            qa[mt][kt2][3] = *(const uint32_t*)(qp1 + kt2 * 16 + 8 + 2 * q);
        }
    }

    const int koff = ((lane & 7) + ((lane >> 4) << 3)) * 40 + (((lane >> 3) & 1) << 3);
    const int voff = ((lane & 7) + (((lane >> 3) & 1) << 3)) * 40 + ((lane >> 4) << 3);
    const size_t kvbase = (size_t)(j * SS) * CC + n * HD;

    float m_[2][2], l_[2][2];
    float4 o_[2][4];
    #pragma unroll
    for (int mt = 0; mt < 2; mt++) {
        m_[mt][0] = m_[mt][1] = -1e30f;
        l_[mt][0] = l_[mt][1] = 0.f;
        #pragma unroll
        for (int nt = 0; nt < 4; nt++) o_[mt][nt] = make_float4(0.f, 0.f, 0.f, 0.f);
    }

    auto stage = [&](int c, int buf) {
        #pragma unroll
        for (int i = 0; i < 2; i++) {
            int id = t + i * 128;
            int row = id >> 2, seg = id & 3;
            uint32_t kdst = smemB + (buf * 2560 + row * 40 + seg * 8) * 2;
            CP_ASYNC16(kdst, kt + kvbase + (size_t)(c * 64 + row) * CC + seg * 8);
            uint32_t vdst = smemB + ((5120 + buf * 2560) + row * 40 + seg * 8) * 2;
            CP_ASYNC16(vdst, vt + kvbase + (size_t)(c * 64 + row) * CC + seg * 8);
        }
        #pragma unroll
        for (int i = 0; i < 8; i++) {
            int id = t + i * 128;
            int brow = id >> 4, bseg = id & 15;
            uint32_t bdst = smemB + ((10240 + buf * 8704) + brow * 136 + bseg * 8) * 2;
            CP_ASYNC16(bdst, bias_h + (size_t)n * MTOT +
                             (size_t)(c * 64 + brow) * SS + ih * 128 + bseg * 8);
        }
    };

    stage(0, 0); CP_COMMIT();
    stage(1, 1); CP_COMMIT();

    for (int c = 0; c < 4; c++) {
        const int buf = c & 1;
        if (c < 3) { CP_WAIT(1); } else { CP_WAIT(0); }
        __syncthreads();

        const uint32_t kB = smemB + (buf * 2560 + koff) * 2;
        const uint32_t vB = smemB + ((5120 + buf * 2560) + voff) * 2;
        const __half* Bsl = hsm2 + 10240 + buf * 8704;

        float4 sc[2][8];
        #pragma unroll
        for (int mt = 0; mt < 2; mt++) {
            int i0l = w * 32 + mt * 16 + g;
            #pragma unroll
            for (int nt = 0; nt < 8; nt++) {
                int kl = nt * 8 + 2 * q;
                const __half* b0p = Bsl + kl * 136 + i0l;
                const __half* b1p = b0p + 136;
                sc[mt][nt].x = __half2float(b0p[0]);
                sc[mt][nt].y = __half2float(b1p[0]);
                sc[mt][nt].z = __half2float(b0p[8]);
                sc[mt][nt].w = __half2float(b1p[8]);
            }
        }

        #pragma unroll
        for (int kt2 = 0; kt2 < 2; kt2++) {
            #pragma unroll
            for (int ntp = 0; ntp < 4; ntp++) {
                uint32_t b0, b1, b2, b3;
                LDSM_X4(b0, b1, b2, b3, kB + (ntp * 640 + kt2 * 16) * 2);
                mma_f16(sc[0][2*ntp],   qa[0][kt2][0], qa[0][kt2][1], qa[0][kt2][2], qa[0][kt2][3], b0, b1);
                mma_f16(sc[0][2*ntp+1], qa[0][kt2][0], qa[0][kt2][1], qa[0][kt2][2], qa[0][kt2][3], b2, b3);
                mma_f16(sc[1][2*ntp],   qa[1][kt2][0], qa[1][kt2][1], qa[1][kt2][2], qa[1][kt2][3], b0, b1);
                mma_f16(sc[1][2*ntp+1], qa[1][kt2][0], qa[1][kt2][1], qa[1][kt2][2], qa[1][kt2][3], b2, b3);
            }
        }

        float mx[2][2] = {{-1e30f, -1e30f}, {-1e30f, -1e30f}};
        #pragma unroll
        for (int mt = 0; mt < 2; mt++)
            #pragma unroll
            for (int nt = 0; nt < 8; nt++) {
                float4 s = sc[mt][nt];
                mx[mt][0] = fmaxf(mx[mt][0], fmaxf(s.x, s.y));
                mx[mt][1] = fmaxf(mx[mt][1], fmaxf(s.z, s.w));
            }
        #pragma unroll
        for (int mt = 0; mt < 2; mt++)
            #pragma unroll
            for (int h = 0; h < 2; h++) {
                float v = mx[mt][h];
                v = fmaxf(v, __shfl_xor_sync(0xffffffffu, v, 1));
                v = fmaxf(v, __shfl_xor_sync(0xffffffffu, v, 2));
                mx[mt][h] = v;
            }

        float al[2][2], mn[2][2];
        #pragma unroll
        for (int mt = 0; mt < 2; mt++)
            #pragma unroll
            for (int h = 0; h < 2; h++) {
                mn[mt][h] = fmaxf(m_[mt][h], mx[mt][h]);
                al[mt][h] = fexp2(m_[mt][h] - mn[mt][h]);
                m_[mt][h] = mn[mt][h];
            }

        float rs_[2][2] = {{0.f, 0.f}, {0.f, 0.f}};
        #pragma unroll
        for (int mt = 0; mt < 2; mt++) {
            #pragma unroll
            for (int nt = 0; nt < 8; nt++) {
                float4 s = sc[mt][nt];
                s.x = fexp2(s.x - mn[mt][0]);
                s.y = fexp2(s.y - mn[mt][0]);
                s.z = fexp2(s.z - mn[mt][1]);
                s.w = fexp2(s.w - mn[mt][1]);
                sc[mt][nt] = s;
                rs_[mt][0] += s.x + s.y;
                rs_[mt][1] += s.z + s.w;
            }
        }
        #pragma unroll
        for (int mt = 0; mt < 2; mt++)
            #pragma unroll
            for (int h = 0; h < 2; h++) {
                float v = rs_[mt][h];
                v += __shfl_xor_sync(0xffffffffu, v, 1);
                v += __shfl_xor_sync(0xffffffffu, v, 2);
                l_[mt][h] = fmaf(l_[mt][h], al[mt][h], v);
            }

        #pragma unroll
        for (int mt = 0; mt < 2; mt++)
            #pragma unroll
            for (int nt = 0; nt < 4; nt++) {
                o_[mt][nt].x *= al[mt][0];
                o_[mt][nt].y *= al[mt][0];
                o_[mt][nt].z *= al[mt][1];
                o_[mt][nt].w *= al[mt][1];
            }

        #pragma unroll
        for (int kt2 = 0; kt2 < 4; kt2++) {
            uint32_t pa[2][4];
            #pragma unroll
            for (int mt = 0; mt < 2; mt++) {
                float4 p0 = sc[mt][2 * kt2];
                float4 p1 = sc[mt][2 * kt2 + 1];
                pa[mt][0] = f16x2(p0.y, p0.x);
                pa[mt][1] = f16x2(p0.w, p0.z);
                pa[mt][2] = f16x2(p1.y, p1.x);
                pa[mt][3] = f16x2(p1.w, p1.z);
            }
            #pragma unroll
            for (int db = 0; db < 2; db++) {
                uint32_t b0, b1, b2, b3;
                LDSM_X4_T(b0, b1, b2, b3, vB + (kt2 * 640 + db * 16) * 2);
                mma_f16(o_[0][2*db],   pa[0][0], pa[0][1], pa[0][2], pa[0][3], b0, b1);
                mma_f16(o_[0][2*db+1], pa[0][0], pa[0][1], pa[0][2], pa[0][3], b2, b3);
                mma_f16(o_[1][2*db],   pa[1][0], pa[1][1], pa[1][2], pa[1][3], b0, b1);
                mma_f16(o_[1][2*db+1], pa[1][0], pa[1][1], pa[1][2], pa[1][3], b2, b3);
            }
        }

        __syncthreads();
        if (c + 2 < 4) { stage(c + 2, buf); CP_COMMIT(); }
    }

    // ---- epilogue: O/l, gate (fp16), store fp16 ----
    #pragma unroll
    for (int mt = 0; mt < 2; mt++) {
        float i0v = 1.f / l_[mt][0];
        float i1v = 1.f / l_[mt][1];
        size_t r0 = (size_t)(j * SS + I0 + mt * 16 + g) * CC + n * HD;
        size_t r1 = r0 + 8 * CC;
        #pragma unroll
        for (int nt2 = 0; nt2 < 4; nt2++) {
            int col = nt2 * 8 + 2 * q;
            float2 g0 = __half22float2(*(const __half2*)(gt + r0 + col));
            float2 g1 = __half22float2(*(const __half2*)(gt + r1 + col));
            float4 o4 = o_[mt][nt2];
            *(uint32_t*)(og + r0 + col) = f16x2(o4.y * i0v * g0.y, o4.x * i0v * g0.x);
            *(uint32_t*)(og + r1 + col) = f16x2(o4.w * i1v * g1.y, o4.z * i1v * g1.x);
        }
    }
}

// ---------------- launch -------------------------------------------------------
extern "C" void kernel_launch(void* const* d_in, const int* in_sizes, int n_in,
                              void* d_out, int out_size) {
    const float* pair  = (const float*)d_in[0];
    const float* gamma = (const float*)d_in[1];
    const float* beta  = (const float*)d_in[2];
    const float* Wq    = (const float*)d_in[3];
    const float* Wk    = (const float*)d_in[4];
    const float* Wv    = (const float*)d_in[5];
    const float* Wb    = (const float*)d_in[6];
    const float* Wg    = (const float*)d_in[7];
    const float* bg    = (const float*)d_in[8];
    const float* Wo    = (const float*)d_in[9];
    const float* bo    = (const float*)d_in[10];
    float* out = (float*)d_out;

    float* base = nullptr;
    cudaGetSymbolAddress((void**)&base, g_scratch);
    __half* qt     = (__half*)(base);
    __half* kt     = (__half*)(base + 4194304);
    __half* vt     = (__half*)(base + 8388608);
    __half* gt     = (__half*)(base + 12582912);
    __half* og     = (__half*)(base + 16777216);
    __half* bias_h = (__half*)(base + 20971520);
    __half* w16    = (__half*)(base + 21102592);

    cudaFuncSetAttribute(fused_qkvg_kernel,
                         cudaFuncAttributeMaxDynamicSharedMemorySize, HGEMM_SMEM);
    cudaFuncSetAttribute(hgemm_out_kernel,
                         cudaFuncAttributeMaxDynamicSharedMemorySize, HGEMM_SMEM);
    cudaFuncSetAttribute(attn_mma_kernel,
                         cudaFuncAttributeMaxDynamicSharedMemorySize, ATT_SMEM_BYTES);

    wconv_kernel<<<80, 256>>>(Wq, Wk, Wv, Wg, Wo, w16);

    FusedArgs fa;
    fa.pair = pair; fa.gamma = gamma; fa.beta = beta;
    fa.W16[0] = w16;             fa.W16[1] = w16 + 16384;
    fa.W16[2] = w16 + 2 * 16384; fa.W16[3] = w16 + 3 * 16384;
    fa.out[0] = qt; fa.out[1] = kt; fa.out[2] = vt; fa.out[3] = gt;
    fa.bias[0] = nullptr; fa.bias[1] = nullptr; fa.bias[2] = nullptr; fa.bias[3] = bg;
    fa.oscale[0] = ATT_SCALE * LOG2E; fa.oscale[1] = 1.f; fa.oscale[2] = 1.f; fa.oscale[3] = 1.f;
    fa.sig[0] = 0; fa.sig[1] = 0; fa.sig[2] = 0; fa.sig[3] = 1;
    fa.Wb = Wb; fa.bias_h = bias_h;
    fused_qkvg_kernel<<<MTOT / 128, 256, HGEMM_SMEM>>>(fa);

    attn_mma_kernel<<<dim3(SS, 2, NH), 128, ATT_SMEM_BYTES>>>(qt, kt, vt, gt, bias_h, og);

    GemmArgs oa;
    oa.A = og;
    oa.W16 = w16 + 4 * 16384;
    oa.out = out;
    oa.bias = bo;
    hgemm_out_kernel<<<MTOT / 128, 256, HGEMM_SMEM>>>(oa);
}

// round 16
// speedup vs baseline: 2.2459x; 1.0356x over previous
#include <cuda_runtime.h>
#include <cuda_fp16.h>
#include <math.h>
#include <stdint.h>

#define SS 256       // sequence
#define CC 128       // channels
#define NH 4
#define HD 32
#define MTOT (SS*SS) // 65536
#define ATT_SCALE 0.17677669529663687f  // 1/sqrt(32)
#define LOG2E 1.4426950408889634f
#define LN_EPS 1e-5f

// ---------------- scratch (offsets in floats) ----------------------------------
//   qt   : [0,        4194304)   fp16 (8388608 halves), row = j*S + i (pre-scaled ATT_SCALE*LOG2E)
//   kt   : [4194304,  8388608)   fp16
//   vt   : [8388608, 12582912)   fp16
//   gt   : [12582912,16777216)   fp16
//   og   : [16777216,20971520)   fp16 gated attention output
//   bias : [20971520,21102592)   fp16 [n][i][k] (NH*MTOT = 262144 halves), x LOG2E
//   w16  : [21102592,21143552)   fp16 weights: Wq,Wk,Wv,Wg,Wo (16384 halves each)
__device__ float g_scratch[21143552];

__device__ __forceinline__ float fexp2(float x) {
    float r;
    asm("ex2.approx.ftz.f32 %0, %1;" : "=f"(r) : "f"(x));
    return r;
}

// pack two fp32 -> f16x2 (lo = second operand) — empirically validated in R8/R9.
__device__ __forceinline__ uint32_t f16x2(float hi, float lo) {
    uint32_t r;
    asm("cvt.rn.f16x2.f32 %0, %1, %2;" : "=r"(r) : "f"(hi), "f"(lo));
    return r;
}

__device__ __forceinline__ void mma_f16(float4& c, uint32_t a0, uint32_t a1,
                                        uint32_t a2, uint32_t a3,
                                        uint32_t b0, uint32_t b1) {
    asm volatile(
        "mma.sync.aligned.m16n8k16.row.col.f32.f16.f16.f32 "
        "{%0,%1,%2,%3}, {%4,%5,%6,%7}, {%8,%9}, {%0,%1,%2,%3};"
        : "+f"(c.x), "+f"(c.y), "+f"(c.z), "+f"(c.w)
        : "r"(a0), "r"(a1), "r"(a2), "r"(a3), "r"(b0), "r"(b1));
}

#define LDSM_X4(d0,d1,d2,d3,a) \
    asm volatile("ldmatrix.sync.aligned.m8n8.x4.shared.b16 {%0,%1,%2,%3}, [%4];" \
                 : "=r"(d0),"=r"(d1),"=r"(d2),"=r"(d3) : "r"(a))
#define LDSM_X4_T(d0,d1,d2,d3,a) \
    asm volatile("ldmatrix.sync.aligned.m8n8.x4.trans.shared.b16 {%0,%1,%2,%3}, [%4];" \
                 : "=r"(d0),"=r"(d1),"=r"(d2),"=r"(d3) : "r"(a))

#define CP_ASYNC16(dst, src) \
    asm volatile("cp.async.ca.shared.global [%0], [%1], 16;" :: "r"(dst), "l"(src))
#define CP_COMMIT() asm volatile("cp.async.commit_group;")
#define CP_WAIT(n)  asm volatile("cp.async.wait_group %0;" :: "n"(n))

// ---------------- weight conversion: 5 x [128,128] fp32 -> fp16 ----------------
__global__ void wconv_kernel(const float* __restrict__ Wq, const float* __restrict__ Wk,
                             const float* __restrict__ Wv, const float* __restrict__ Wg,
                             const float* __restrict__ Wo, __half* __restrict__ dst) {
    int id = blockIdx.x * 256 + threadIdx.x;      // 0..20479 float4s
    const float* srcs[5] = {Wq, Wk, Wv, Wg, Wo};
    int wsel = id >> 12, off = id & 4095;
    float4 v = ((const float4*)srcs[wsel])[off];
    uint2 p;
    p.x = f16x2(v.y, v.x);
    p.y = f16x2(v.w, v.z);
    *(uint2*)(dst + wsel * 16384 + off * 4) = p;
}

// ---------------- fused LN + QKVG GEMM + bias projection -----------------------
// One block = 128 input rows. LN computed in-flight while staging the fp16 A
// tile; bias_h (z@Wb x LOG2E, layout [n][i][k]) from the same fp32 z values.
// Weights (fp16, pre-converted) staged via cp.async double-buffered pipeline.
struct FusedArgs {
    const float*  pair;
    const float*  gamma;
    const float*  beta;
    const __half* W16[4];
    __half*       out[4];
    const float*  bias[4];
    float         oscale[4];
    int           sig[4];
    const float*  Wb;
    __half*       bias_h;
};

#define HGEMM_SMEM (3 * 17408 * 2)   // 104448 bytes
#define HOUT_SMEM  (2 * 17408 * 2)   // 69632 bytes

__global__ void __launch_bounds__(256, 2)
fused_qkvg_kernel(FusedArgs fa) {
    extern __shared__ __half hsm[];
    __half* Ah = hsm;                 // 128 * 136
    __half* Bbuf0 = hsm + 17408;
    __half* Bbuf1 = hsm + 34816;
    const uint32_t b0B = (uint32_t)__cvta_generic_to_shared(Bbuf0);
    const uint32_t b1B = (uint32_t)__cvta_generic_to_shared(Bbuf1);
    const int t = threadIdx.x;
    const int lane = t & 31, warp = t >> 5;
    const int wm = warp & 3, wn = warp >> 2;
    const int m0w = wm * 32, n0w = wn * 64;
    const int g = lane >> 2, q = lane & 3;
    const int row0 = blockIdx.x * 128;

    // ---- async-stage weight w into buffer buf (fp16 src, raw 16B copies) ----
    auto stageW = [&](int w, int buf) {
        const __half* W = fa.W16[w];
        const uint32_t dstB = buf ? b1B : b0B;
        #pragma unroll
        for (int i = 0; i < 8; i++) {
            int id = t + i * 256;            // 0..2047 16B chunks
            int kk = id >> 4, seg = id & 15;
            CP_ASYNC16(dstB + (kk * 136 + seg * 8) * 2, W + kk * 128 + seg * 8);
        }
    };
    stageW(0, 0); CP_COMMIT();

    // ---- LN pass 1: stats (2 threads per row, 64 channels each) ----
    const int arow = t >> 1, ahalf = t & 1;
    const float4* prow = (const float4*)(fa.pair + (size_t)(row0 + arow) * CC + ahalf * 64);
    float s = 0.f, sq = 0.f;
    #pragma unroll
    for (int i = 0; i < 16; i++) {
        float4 v = prow[i];
        s  += v.x + v.y + v.z + v.w;
        sq += v.x*v.x + v.y*v.y + v.z*v.z + v.w*v.w;
    }
    s  += __shfl_xor_sync(0xffffffffu, s,  1);
    sq += __shfl_xor_sync(0xffffffffu, sq, 1);
    const float mu = s * (1.0f / CC);
    const float rs = rsqrtf(sq * (1.0f / CC) - mu * mu + LN_EPS);

    // ---- LN pass 2: normalize, store fp16 A tile, accumulate bias dots ----
    const float4* gam4 = (const float4*)(fa.gamma + ahalf * 64);
    const float4* bet4 = (const float4*)(fa.beta  + ahalf * 64);
    const float4* Wb4  = (const float4*)fa.Wb;
    float4 bacc = make_float4(0.f, 0.f, 0.f, 0.f);
    #pragma unroll
    for (int i = 0; i < 16; i++) {
        float4 v = prow[i];
        float4 g4 = gam4[i];
        float4 b4 = bet4[i];
        float z0 = (v.x - mu) * rs * g4.x + b4.x;
        float z1 = (v.y - mu) * rs * g4.y + b4.y;
        float z2 = (v.z - mu) * rs * g4.z + b4.z;
        float z3 = (v.w - mu) * rs * g4.w + b4.w;
        int c0 = ahalf * 64 + i * 4;
        uint2 p;
        p.x = f16x2(z1, z0);
        p.y = f16x2(z3, z2);
        *(uint2*)(Ah + arow * 136 + c0) = p;
        float4 w0 = Wb4[c0], w1 = Wb4[c0 + 1], w2 = Wb4[c0 + 2], w3 = Wb4[c0 + 3];
        bacc.x += z0*w0.x + z1*w1.x + z2*w2.x + z3*w3.x;
        bacc.y += z0*w0.y + z1*w1.y + z2*w2.y + z3*w3.y;
        bacc.z += z0*w0.z + z1*w1.z + z2*w2.z + z3*w3.z;
        bacc.w += z0*w0.w + z1*w1.w + z2*w2.w + z3*w3.w;
    }
    bacc.x += __shfl_xor_sync(0xffffffffu, bacc.x, 1);
    bacc.y += __shfl_xor_sync(0xffffffffu, bacc.y, 1);
    bacc.z += __shfl_xor_sync(0xffffffffu, bacc.z, 1);
    bacc.w += __shfl_xor_sync(0xffffffffu, bacc.w, 1);
    if (ahalf == 0) {
        int R = row0 + arow;                // R = i*256 + j -> bias_h[n][i][k=j]
        fa.bias_h[0 * MTOT + R] = __float2half(bacc.x * LOG2E);
        fa.bias_h[1 * MTOT + R] = __float2half(bacc.y * LOG2E);
        fa.bias_h[2 * MTOT + R] = __float2half(bacc.z * LOG2E);
        fa.bias_h[3 * MTOT + R] = __float2half(bacc.w * LOG2E);
    }

    uint32_t aBase[2];
    #pragma unroll
    for (int mt = 0; mt < 2; mt++)
        aBase[mt] = (uint32_t)__cvta_generic_to_shared(
            Ah + (m0w + 16 * mt + (lane & 15)) * 136 + (lane >> 4) * 8);
    const int krow_l = (lane & 7) + (((lane & 15) >> 3) << 3);
    const int ncol_l = (lane >> 4) * 8;
    uint32_t bBase[2];
    bBase[0] = b0B + (krow_l * 136 + n0w + ncol_l) * 2;
    bBase[1] = b1B + (krow_l * 136 + n0w + ncol_l) * 2;

    for (int w = 0; w < 4; w++) {
        if (w < 3) { stageW(w + 1, (w + 1) & 1); CP_COMMIT(); }
        if (w < 3) { CP_WAIT(1); } else { CP_WAIT(0); }
        __syncthreads();

        float4 acc[2][8];
        #pragma unroll
        for (int mt = 0; mt < 2; mt++)
            #pragma unroll
            for (int nt = 0; nt < 8; nt++) acc[mt][nt] = make_float4(0.f, 0.f, 0.f, 0.f);

        const uint32_t bB = bBase[w & 1];
        #pragma unroll
        for (int step = 0; step < 8; step++) {
            uint32_t a0[4], a1[4];
            LDSM_X4(a0[0], a0[1], a0[2], a0[3], aBase[0] + step * 32);
            LDSM_X4(a1[0], a1[1], a1[2], a1[3], aBase[1] + step * 32);
            #pragma unroll
            for (int p2 = 0; p2 < 4; p2++) {
                uint32_t b0, b1, b2, b3;
                LDSM_X4_T(b0, b1, b2, b3, bB + (step * 2176 + p2 * 16) * 2);
                mma_f16(acc[0][2*p2],   a0[0], a0[1], a0[2], a0[3], b0, b1);
                mma_f16(acc[0][2*p2+1], a0[0], a0[1], a0[2], a0[3], b2, b3);
                mma_f16(acc[1][2*p2],   a1[0], a1[1], a1[2], a1[3], b0, b1);
                mma_f16(acc[1][2*p2+1], a1[0], a1[1], a1[2], a1[3], b2, b3);
            }
        }

        const float* bias = fa.bias[w];
        const int sig = fa.sig[w];
        const float osc = fa.oscale[w];
        __half* o = fa.out[w];
        float2 bv[8];
        #pragma unroll
        for (int nt = 0; nt < 8; nt++) {
            if (bias) bv[nt] = *(const float2*)(bias + n0w + nt * 8 + 2 * q);
            else      bv[nt] = make_float2(0.f, 0.f);
        }
        #pragma unroll
        for (int mt = 0; mt < 2; mt++) {
            int r  = row0 + m0w + mt * 16 + g;
            int r2 = r + 8;
            int or0 = ((r  & 255) << 8) | (r  >> 8);
            int or1 = ((r2 & 255) << 8) | (r2 >> 8);
            #pragma unroll
            for (int nt = 0; nt < 8; nt++) {
                int col = n0w + nt * 8 + 2 * q;
                float4 c = acc[mt][nt];
                float v0 = (c.x + bv[nt].x) * osc, v1 = (c.y + bv[nt].y) * osc;
                float v2 = (c.z + bv[nt].x) * osc, v3 = (c.w + bv[nt].y) * osc;
                if (sig) {
                    v0 = 1.0f / (1.0f + __expf(-v0));
                    v1 = 1.0f / (1.0f + __expf(-v1));
                    v2 = 1.0f / (1.0f + __expf(-v2));
                    v3 = 1.0f / (1.0f + __expf(-v3));
                }
                *(uint32_t*)(o + (size_t)or0 * CC + col) = f16x2(v1, v0);
                *(uint32_t*)(o + (size_t)or1 * CC + col) = f16x2(v3, v2);
            }
        }
        __syncthreads();
    }
}

// ---------------- out-projection GEMM: og fp16 -> out fp32 ---------------------
struct GemmArgs {
    const __half* A;     // og fp16
    const __half* W16;   // Wo fp16
    float*        out;
    const float*  bias;
};

__global__ void __launch_bounds__(256, 2)
hgemm_out_kernel(GemmArgs ga) {
    extern __shared__ __half hsm[];
    __half* Ah = hsm;
    __half* Bbuf0 = hsm + 17408;
    const uint32_t ahB = (uint32_t)__cvta_generic_to_shared(Ah);
    const uint32_t b0B = (uint32_t)__cvta_generic_to_shared(Bbuf0);
    const int t = threadIdx.x;
    const int lane = t & 31, warp = t >> 5;
    const int wm = warp & 3, wn = warp >> 2;
    const int m0w = wm * 32, n0w = wn * 64;
    const int g = lane >> 2, q = lane & 3;
    const int row0 = blockIdx.x * 128;

    #pragma unroll
    for (int i = 0; i < 8; i++) {
        int id = t + i * 256;            // 0..2047 16B chunks
        int r = id >> 4, seg = id & 15;
        CP_ASYNC16(ahB + (r * 136 + seg * 8) * 2, ga.A + (size_t)(row0 + r) * CC + seg * 8);
    }
    #pragma unroll
    for (int i = 0; i < 8; i++) {
        int id = t + i * 256;
        int kk = id >> 4, seg = id & 15;
        CP_ASYNC16(b0B + (kk * 136 + seg * 8) * 2, ga.W16 + kk * 128 + seg * 8);
    }
    CP_COMMIT(); CP_WAIT(0);
    __syncthreads();

    uint32_t aBase[2];
    #pragma unroll
    for (int mt = 0; mt < 2; mt++)
        aBase[mt] = ahB + ((m0w + 16 * mt + (lane & 15)) * 136 + (lane >> 4) * 8) * 2;
    const int krow_l = (lane & 7) + (((lane & 15) >> 3) << 3);
    const int ncol_l = (lane >> 4) * 8;
    const uint32_t bB = b0B + (krow_l * 136 + n0w + ncol_l) * 2;

    float4 acc[2][8];
    #pragma unroll
    for (int mt = 0; mt < 2; mt++)
        #pragma unroll
        for (int nt = 0; nt < 8; nt++) acc[mt][nt] = make_float4(0.f, 0.f, 0.f, 0.f);

    #pragma unroll
    for (int step = 0; step < 8; step++) {
        uint32_t a0[4], a1[4];
        LDSM_X4(a0[0], a0[1], a0[2], a0[3], aBase[0] + step * 32);
        LDSM_X4(a1[0], a1[1], a1[2], a1[3], aBase[1] + step * 32);
        #pragma unroll
        for (int p2 = 0; p2 < 4; p2++) {
            uint32_t b0, b1, b2, b3;
            LDSM_X4_T(b0, b1, b2, b3, bB + (step * 2176 + p2 * 16) * 2);
            mma_f16(acc[0][2*p2],   a0[0], a0[1], a0[2], a0[3], b0, b1);
            mma_f16(acc[0][2*p2+1], a0[0], a0[1], a0[2], a0[3], b2, b3);
            mma_f16(acc[1][2*p2],   a1[0], a1[1], a1[2], a1[3], b0, b1);
            mma_f16(acc[1][2*p2+1], a1[0], a1[1], a1[2], a1[3], b2, b3);
        }
    }

    float2 bv[8];
    #pragma unroll
    for (int nt = 0; nt < 8; nt++)
        bv[nt] = *(const float2*)(ga.bias + n0w + nt * 8 + 2 * q);
    #pragma unroll
    for (int mt = 0; mt < 2; mt++) {
        int r  = row0 + m0w + mt * 16 + g;
        int r2 = r + 8;
        int or0 = ((r  & 255) << 8) | (r  >> 8);
        int or1 = ((r2 & 255) << 8) | (r2 >> 8);
        #pragma unroll
        for (int nt = 0; nt < 8; nt++) {
            int col = n0w + nt * 8 + 2 * q;
            float4 c = acc[mt][nt];
            *(float2*)(ga.out + (size_t)or0 * CC + col) =
                make_float2(c.x + bv[nt].x, c.y + bv[nt].y);
            *(float2*)(ga.out + (size_t)or1 * CC + col) =
                make_float2(c.z + bv[nt].x, c.w + bv[nt].y);
        }
    }
}

// ---------------- all-fp16 MMA flash attention ---------------------------------
// 128-thread CTAs (4 warps x 32 query rows), 2 CTAs/SM; grid (j, ih=2, n).
// smem (halves): Kh[2] [0,5120) stride 40; Vh[2] [5120,10240) stride 40;
// bias slab[2] [10240,28672): [i=128][k=64] stride 72 (conflict-free half2 reads).
#define ATT_SMEM_BYTES (28672 * 2)   // 57344 bytes
__global__ void __launch_bounds__(128, 2)
attn_mma_kernel(const __half* __restrict__ qt, const __half* __restrict__ kt,
                const __half* __restrict__ vt, const __half* __restrict__ gt,
                const __half* __restrict__ bias_h, __half* __restrict__ og) {
    extern __shared__ __half hsm2[];
    const uint32_t smemB = (uint32_t)__cvta_generic_to_shared(hsm2);

    const int j = blockIdx.x, ih = blockIdx.y, n = blockIdx.z;
    const int t = threadIdx.x;
    const int lane = t & 31, w = t >> 5;
    const int g = lane >> 2, q = lane & 3;
    const int I0 = ih * 128 + w * 32;

    uint32_t qa[2][2][4];
    #pragma unroll
    for (int mt = 0; mt < 2; mt++) {
        const __half* qp0 = qt + (size_t)(j * SS + I0 + mt * 16 + g) * CC + n * HD;
        const __half* qp1 = qp0 + 8 * CC;
        #pragma unroll
        for (int kt2 = 0; kt2 < 2; kt2++) {
            qa[mt][kt2][0] = *(const uint32_t*)(qp0 + kt2 * 16 + 2 * q);
            qa[mt][kt2][1] = *(const uint32_t*)(qp1 + kt2 * 16 + 2 * q);
            qa[mt][kt2][2] = *(const uint32_t*)(qp0 + kt2 * 16 + 8 + 2 * q);
            qa[mt][kt2][3] = *(const uint32_t*)(qp1 + kt2 * 16 + 8 + 2 * q);
        }
    }

    const int koff = ((lane & 7) + ((lane >> 4) << 3)) * 40 + (((lane >> 3) & 1) << 3);
    const int voff = ((lane & 7) + (((lane >> 3) & 1) << 3)) * 40 + ((lane >> 4) << 3);
    const size_t kvbase = (size_t)(j * SS) * CC + n * HD;

    float m_[2][2], l_[2][2];
    float4 o_[2][4];
    #pragma unroll
    for (int mt = 0; mt < 2; mt++) {
        m_[mt][0] = m_[mt][1] = -1e30f;
        l_[mt][0] = l_[mt][1] = 0.f;
        #pragma unroll
        for (int nt = 0; nt < 4; nt++) o_[mt][nt] = make_float4(0.f, 0.f, 0.f, 0.f);
    }

    auto stage = [&](int c, int buf) {
        #pragma unroll
        for (int i = 0; i < 2; i++) {
            int id = t + i * 128;
            int row = id >> 2, seg = id & 3;
            uint32_t kdst = smemB + (buf * 2560 + row * 40 + seg * 8) * 2;
            CP_ASYNC16(kdst, kt + kvbase + (size_t)(c * 64 + row) * CC + seg * 8);
            uint32_t vdst = smemB + ((5120 + buf * 2560) + row * 40 + seg * 8) * 2;
            CP_ASYNC16(vdst, vt + kvbase + (size_t)(c * 64 + row) * CC + seg * 8);
        }
        // bias slab: [i=128][k=64] stride 72, src bias_h[n][ih*128+i][c*64..+64)
        #pragma unroll
        for (int i = 0; i < 8; i++) {
            int id = t + i * 128;
            int brow = id >> 3, bseg = id & 7;
            uint32_t bdst = smemB + ((10240 + buf * 9216) + brow * 72 + bseg * 8) * 2;
            CP_ASYNC16(bdst, bias_h + (size_t)n * MTOT +
                             (size_t)(ih * 128 + brow) * SS + c * 64 + bseg * 8);
        }
    };

    stage(0, 0); CP_COMMIT();
    stage(1, 1); CP_COMMIT();

    for (int c = 0; c < 4; c++) {
        const int buf = c & 1;
        if (c < 3) { CP_WAIT(1); } else { CP_WAIT(0); }
        __syncthreads();

        const uint32_t kB = smemB + (buf * 2560 + koff) * 2;
        const uint32_t vB = smemB + ((5120 + buf * 2560) + voff) * 2;
        const __half* Bsl = hsm2 + 10240 + buf * 9216;

        // ---- init S accumulator from bias slab (half2 loads, keys adjacent) ----
        float4 sc[2][8];
        #pragma unroll
        for (int mt = 0; mt < 2; mt++) {
            int i0l = w * 32 + mt * 16 + g;
            const __half2* bp0 = (const __half2*)(Bsl + i0l * 72);
            const __half2* bp8 = (const __half2*)(Bsl + (i0l + 8) * 72);
            #pragma unroll
            for (int nt = 0; nt < 8; nt++) {
                float2 f0 = __half22float2(bp0[nt * 4 + q]);
                float2 f1 = __half22float2(bp8[nt * 4 + q]);
                sc[mt][nt] = make_float4(f0.x, f0.y, f1.x, f1.y);
            }
        }

        #pragma unroll
        for (int kt2 = 0; kt2 < 2; kt2++) {
            #pragma unroll
            for (int ntp = 0; ntp < 4; ntp++) {
                uint32_t b0, b1, b2, b3;
                LDSM_X4(b0, b1, b2, b3, kB + (ntp * 640 + kt2 * 16) * 2);
                mma_f16(sc[0][2*ntp],   qa[0][kt2][0], qa[0][kt2][1], qa[0][kt2][2], qa[0][kt2][3], b0, b1);
                mma_f16(sc[0][2*ntp+1], qa[0][kt2][0], qa[0][kt2][1], qa[0][kt2][2], qa[0][kt2][3], b2, b3);
                mma_f16(sc[1][2*ntp],   qa[1][kt2][0], qa[1][kt2][1], qa[1][kt2][2], qa[1][kt2][3], b0, b1);
                mma_f16(sc[1][2*ntp+1], qa[1][kt2][0], qa[1][kt2][1], qa[1][kt2][2], qa[1][kt2][3], b2, b3);
            }
        }

        float mx[2][2] = {{-1e30f, -1e30f}, {-1e30f, -1e30f}};
        #pragma unroll
        for (int mt = 0; mt < 2; mt++)
            #pragma unroll
            for (int nt = 0; nt < 8; nt++) {
                float4 s = sc[mt][nt];
                mx[mt][0] = fmaxf(mx[mt][0], fmaxf(s.x, s.y));
                mx[mt][1] = fmaxf(mx[mt][1], fmaxf(s.z, s.w));
            }
        #pragma unroll
        for (int mt = 0; mt < 2; mt++)
            #pragma unroll
            for (int h = 0; h < 2; h++) {
                float v = mx[mt][h];
                v = fmaxf(v, __shfl_xor_sync(0xffffffffu, v, 1));
                v = fmaxf(v, __shfl_xor_sync(0xffffffffu, v, 2));
                mx[mt][h] = v;
            }

        float al[2][2], mn[2][2];
        #pragma unroll
        for (int mt = 0; mt < 2; mt++)
            #pragma unroll
            for (int h = 0; h < 2; h++) {
                mn[mt][h] = fmaxf(m_[mt][h], mx[mt][h]);
                al[mt][h] = fexp2(m_[mt][h] - mn[mt][h]);
                m_[mt][h] = mn[mt][h];
            }

        float rs_[2][2] = {{0.f, 0.f}, {0.f, 0.f}};
        #pragma unroll
        for (int mt = 0; mt < 2; mt++) {
            #pragma unroll
            for (int nt = 0; nt < 8; nt++) {
                float4 s = sc[mt][nt];
                s.x = fexp2(s.x - mn[mt][0]);
                s.y = fexp2(s.y - mn[mt][0]);
                s.z = fexp2(s.z - mn[mt][1]);
                s.w = fexp2(s.w - mn[mt][1]);
                sc[mt][nt] = s;
                rs_[mt][0] += s.x + s.y;
                rs_[mt][1] += s.z + s.w;
            }
        }
        #pragma unroll
        for (int mt = 0; mt < 2; mt++)
            #pragma unroll
            for (int h = 0; h < 2; h++) {
                float v = rs_[mt][h];
                v += __shfl_xor_sync(0xffffffffu, v, 1);
                v += __shfl_xor_sync(0xffffffffu, v, 2);
                l_[mt][h] = fmaf(l_[mt][h], al[mt][h], v);
            }

        #pragma unroll
        for (int mt = 0; mt < 2; mt++)
            #pragma unroll
            for (int nt = 0; nt < 4; nt++) {
                o_[mt][nt].x *= al[mt][0];
                o_[mt][nt].y *= al[mt][0];
                o_[mt][nt].z *= al[mt][1];
                o_[mt][nt].w *= al[mt][1];
            }

        #pragma unroll
        for (int kt2 = 0; kt2 < 4; kt2++) {
            uint32_t pa[2][4];
            #pragma unroll
            for (int mt = 0; mt < 2; mt++) {
                float4 p0 = sc[mt][2 * kt2];
                float4 p1 = sc[mt][2 * kt2 + 1];
                pa[mt][0] = f16x2(p0.y, p0.x);
                pa[mt][1] = f16x2(p0.w, p0.z);
                pa[mt][2] = f16x2(p1.y, p1.x);
                pa[mt][3] = f16x2(p1.w, p1.z);
            }
            #pragma unroll
            for (int db = 0; db < 2; db++) {
                uint32_t b0, b1, b2, b3;
                LDSM_X4_T(b0, b1, b2, b3, vB + (kt2 * 640 + db * 16) * 2);
                mma_f16(o_[0][2*db],   pa[0][0], pa[0][1], pa[0][2], pa[0][3], b0, b1);
                mma_f16(o_[0][2*db+1], pa[0][0], pa[0][1], pa[0][2], pa[0][3], b2, b3);
                mma_f16(o_[1][2*db],   pa[1][0], pa[1][1], pa[1][2], pa[1][3], b0, b1);
                mma_f16(o_[1][2*db+1], pa[1][0], pa[1][1], pa[1][2], pa[1][3], b2, b3);
            }
        }

        __syncthreads();
        if (c + 2 < 4) { stage(c + 2, buf); CP_COMMIT(); }
    }

    // ---- epilogue: O/l, gate (fp16), store fp16 ----
    #pragma unroll
    for (int mt = 0; mt < 2; mt++) {
        float i0v = 1.f / l_[mt][0];
        float i1v = 1.f / l_[mt][1];
        size_t r0 = (size_t)(j * SS + I0 + mt * 16 + g) * CC + n * HD;
        size_t r1 = r0 + 8 * CC;
        #pragma unroll
        for (int nt2 = 0; nt2 < 4; nt2++) {
            int col = nt2 * 8 + 2 * q;
            float2 g0 = __half22float2(*(const __half2*)(gt + r0 + col));
            float2 g1 = __half22float2(*(const __half2*)(gt + r1 + col));
            float4 o4 = o_[mt][nt2];
            *(uint32_t*)(og + r0 + col) = f16x2(o4.y * i0v * g0.y, o4.x * i0v * g0.x);
            *(uint32_t*)(og + r1 + col) = f16x2(o4.w * i1v * g1.y, o4.z * i1v * g1.x);
        }
    }
}

// ---------------- launch -------------------------------------------------------
extern "C" void kernel_launch(void* const* d_in, const int* in_sizes, int n_in,
                              void* d_out, int out_size) {
    const float* pair  = (const float*)d_in[0];
    const float* gamma = (const float*)d_in[1];
    const float* beta  = (const float*)d_in[2];
    const float* Wq    = (const float*)d_in[3];
    const float* Wk    = (const float*)d_in[4];
    const float* Wv    = (const float*)d_in[5];
    const float* Wb    = (const float*)d_in[6];
    const float* Wg    = (const float*)d_in[7];
    const float* bg    = (const float*)d_in[8];
    const float* Wo    = (const float*)d_in[9];
    const float* bo    = (const float*)d_in[10];
    float* out = (float*)d_out;

    float* base = nullptr;
    cudaGetSymbolAddress((void**)&base, g_scratch);
    __half* qt     = (__half*)(base);
    __half* kt     = (__half*)(base + 4194304);
    __half* vt     = (__half*)(base + 8388608);
    __half* gt     = (__half*)(base + 12582912);
    __half* og     = (__half*)(base + 16777216);
    __half* bias_h = (__half*)(base + 20971520);
    __half* w16    = (__half*)(base + 21102592);

    cudaFuncSetAttribute(fused_qkvg_kernel,
                         cudaFuncAttributeMaxDynamicSharedMemorySize, HGEMM_SMEM);
    cudaFuncSetAttribute(hgemm_out_kernel,
                         cudaFuncAttributeMaxDynamicSharedMemorySize, HOUT_SMEM);
    cudaFuncSetAttribute(attn_mma_kernel,
                         cudaFuncAttributeMaxDynamicSharedMemorySize, ATT_SMEM_BYTES);

    wconv_kernel<<<80, 256>>>(Wq, Wk, Wv, Wg, Wo, w16);

    FusedArgs fa;
    fa.pair = pair; fa.gamma = gamma; fa.beta = beta;
    fa.W16[0] = w16;             fa.W16[1] = w16 + 16384;
    fa.W16[2] = w16 + 2 * 16384; fa.W16[3] = w16 + 3 * 16384;
    fa.out[0] = qt; fa.out[1] = kt; fa.out[2] = vt; fa.out[3] = gt;
    fa.bias[0] = nullptr; fa.bias[1] = nullptr; fa.bias[2] = nullptr; fa.bias[3] = bg;
    fa.oscale[0] = ATT_SCALE * LOG2E; fa.oscale[1] = 1.f; fa.oscale[2] = 1.f; fa.oscale[3] = 1.f;
    fa.sig[0] = 0; fa.sig[1] = 0; fa.sig[2] = 0; fa.sig[3] = 1;
    fa.Wb = Wb; fa.bias_h = bias_h;
    fused_qkvg_kernel<<<MTOT / 128, 256, HGEMM_SMEM>>>(fa);

    attn_mma_kernel<<<dim3(SS, 2, NH), 128, ATT_SMEM_BYTES>>>(qt, kt, vt, gt, bias_h, og);

    GemmArgs oa;
    oa.A = og;
    oa.W16 = w16 + 4 * 16384;
    oa.out = out;
    oa.bias = bo;
    hgemm_out_kernel<<<MTOT / 128, 256, HOUT_SMEM>>>(oa);
}